// round 13
// baseline (speedup 1.0000x reference)
#include <cuda_runtime.h>
#include <cuda_fp16.h>
#include <cstdint>

// ---------------- scratch (device globals; no allocation allowed) ----------
// Activations: [b][plane=16ch][HW px][8 u32 record], record = slot-permuted
// fp16x2 pairs: slot(c) = (c&3)*2+(c>>2) holds channels (c, c+8), c=0..7.
__device__ unsigned g_bufA[16777216];  // conv1 out (8,4pl,65536,8)
__device__ unsigned g_bufP[8388608];   // pooled    (8,8pl,16384,8)
__device__ unsigned g_bufC[16777216];  // conv3 out (8,16pl,16384,8)
__device__ unsigned g_bufD[16777216];  // conv4 out sr pass
__device__ unsigned g_wpk[524288];     // packed fp16 A-fragment weights
__device__ double g_acc[3];            // 0: mse, 1: ssim, 2: perceptual

__global__ void zero_acc_kernel() { g_acc[0]=0.0; g_acc[1]=0.0; g_acc[2]=0.0; }

// ---------------- helpers ----------------
__device__ __forceinline__ float block_reduce_sum256(float v, float* sh, int tid) {
    #pragma unroll
    for (int o = 16; o > 0; o >>= 1) v += __shfl_down_sync(0xffffffffu, v, o);
    if ((tid & 31) == 0) sh[tid >> 5] = v;
    __syncthreads();
    if (tid < 32) {
        v = (tid < 8) ? sh[tid] : 0.0f;
        #pragma unroll
        for (int o = 4; o > 0; o >>= 1) v += __shfl_down_sync(0xffffffffu, v, o);
    }
    return v;
}
__device__ __forceinline__ float block_reduce_sum512(float v, float* sh, int tid) {
    #pragma unroll
    for (int o = 16; o > 0; o >>= 1) v += __shfl_down_sync(0xffffffffu, v, o);
    if ((tid & 31) == 0) sh[tid >> 5] = v;
    __syncthreads();
    if (tid < 32) {
        v = (tid < 16) ? sh[tid] : 0.0f;
        #pragma unroll
        for (int o = 8; o > 0; o >>= 1) v += __shfl_down_sync(0xffffffffu, v, o);
    }
    return v;
}
__device__ __forceinline__ unsigned pack_h2(float lo, float hi) {
    __half2 h = __floats2half2_rn(lo, hi);
    return *(unsigned*)&h;
}
__device__ __forceinline__ float2 unpack_h2(unsigned u) {
    __half2 h = *(__half2*)&u;
    return __half22float2(h);
}
__device__ __forceinline__ float h16r(float x) {
    return __half2float(__float2half_rn(x));
}
__device__ __forceinline__ unsigned hm2(unsigned a, unsigned b) {
    __half2 r = __hmax2(*(__half2*)&a, *(__half2*)&b);
    return *(unsigned*)&r;
}
__device__ __forceinline__ void mma_f16(float* c, const uint4 a, const uint2 b) {
    asm volatile(
        "mma.sync.aligned.m16n8k16.row.col.f32.f16.f16.f32 "
        "{%0,%1,%2,%3}, {%4,%5,%6,%7}, {%8,%9}, {%0,%1,%2,%3};"
        : "+f"(c[0]), "+f"(c[1]), "+f"(c[2]), "+f"(c[3])
        : "r"(a.x), "r"(a.y), "r"(a.z), "r"(a.w), "r"(b.x), "r"(b.y));
}
__device__ __forceinline__ void cp_async16(unsigned dst, const void* src) {
    asm volatile("cp.async.cg.shared.global [%0], [%1], 16;" :: "r"(dst), "l"(src));
}
__device__ __forceinline__ void cp_async16z(unsigned dst, const void* src, bool ok) {
    int sz = ok ? 16 : 0;
    asm volatile("cp.async.cg.shared.global [%0], [%1], 16, %2;"
                 :: "r"(dst), "l"(src), "r"(sz));
}
__device__ __forceinline__ void cp_commit() { asm volatile("cp.async.commit_group;"); }
template<int N> __device__ __forceinline__ void cp_wait() {
    asm volatile("cp.async.wait_group %0;" :: "n"(N));
}
__device__ __forceinline__ int slot_of(int c) { return ((c & 3) << 1) + (c >> 2); }

// ---------------- MSE ----------------
__global__ void mse_kernel(const float* __restrict__ a, const float* __restrict__ b, int n) {
    __shared__ float sh[32];
    float s = 0.0f;
    for (int i = blockIdx.x * blockDim.x + threadIdx.x; i < n; i += gridDim.x * blockDim.x) {
        float d = a[i] - b[i];
        s = fmaf(d, d, s);
    }
    s = block_reduce_sum256(s, sh, threadIdx.x);
    if (threadIdx.x == 0) atomicAdd(&g_acc[0], (double)s);
}

// ---------------- SSIM ----------------
__global__ void ssim_kernel(const float* __restrict__ x, const float* __restrict__ y) {
    __shared__ float sxt[22][23];
    __shared__ float syt[22][23];
    __shared__ float sh[32];
    int b = blockIdx.z;
    int gx0 = blockIdx.x * 16, gy0 = blockIdx.y * 16;
    const float* xb = x + (size_t)b * 65536;
    const float* yb = y + (size_t)b * 65536;
    int tid = threadIdx.y * 16 + threadIdx.x;
    for (int i = tid; i < 22 * 22; i += 256) {
        int rr = i / 22, cc = i - rr * 22;
        int gy = gy0 + rr, gx = gx0 + cc;
        float vx = 0.0f, vy = 0.0f;
        if (gy < 256 && gx < 256) { vx = xb[gy * 256 + gx]; vy = yb[gy * 256 + gx]; }
        sxt[rr][cc] = vx; syt[rr][cc] = vy;
    }
    __syncthreads();
    int i = gy0 + threadIdx.y, j = gx0 + threadIdx.x;
    float S = 0.0f;
    if (i < 250 && j < 250) {
        float sx = 0, sy = 0, sxx = 0, syy = 0, sxy = 0;
        #pragma unroll
        for (int dy = 0; dy < 7; dy++)
            #pragma unroll
            for (int dx = 0; dx < 7; dx++) {
                float a = sxt[threadIdx.y + dy][threadIdx.x + dx];
                float c = syt[threadIdx.y + dy][threadIdx.x + dx];
                sx += a; sy += c;
                sxx = fmaf(a, a, sxx); syy = fmaf(c, c, syy); sxy = fmaf(a, c, sxy);
            }
        const float inv = 1.0f / 49.0f, cn = 49.0f / 48.0f;
        float ux = sx * inv, uy = sy * inv;
        float vx  = cn * (sxx * inv - ux * ux);
        float vy  = cn * (syy * inv - uy * uy);
        float vxy = cn * (sxy * inv - ux * uy);
        const float C1 = 1e-4f, C2 = 9e-4f;
        S = ((2.0f * ux * uy + C1) * (2.0f * vxy + C2)) /
            ((ux * ux + uy * uy + C1) * (vx + vy + C2));
    }
    float tot = block_reduce_sum256(S, sh, tid);
    if (tid == 0) atomicAdd(&g_acc[1], (double)tot);
}

// ---------------- conv1: 1 -> 64 ch, relu, 32B pixel records ----------
__global__ void conv1_kernel(const float* __restrict__ in, const float* __restrict__ w,
                             const float* __restrict__ bias, unsigned* __restrict__ out) {
    __shared__ float sw[576];
    __shared__ float sb[64];
    int tid = threadIdx.x;
    for (int i = tid; i < 576; i += 256) sw[i] = w[i];
    if (tid < 64) sb[tid] = bias[tid];
    __syncthreads();
    int g = blockIdx.x * 256 + tid;
    int x4 = (g & 63) * 4;
    int y  = (g >> 6) & 255;
    int b  = g >> 14;
    const float* ib = in + (size_t)b * 65536;
    float inp[3][6];
    #pragma unroll
    for (int dy = 0; dy < 3; dy++) {
        int gy = y - 1 + dy;
        #pragma unroll
        for (int c = 0; c < 6; c++) {
            int gx = x4 - 1 + c;
            inp[dy][c] = ((unsigned)gy < 256u && (unsigned)gx < 256u) ? ib[gy * 256 + gx] : 0.0f;
        }
    }
    for (int blk = 0; blk < 4; blk++) {
        unsigned rec[4][8];
        for (int c = 0; c < 8; c++) {
            int coL = 16 * blk + c, coH = coL + 8;
            float aL[4], aH[4];
            #pragma unroll
            for (int p = 0; p < 4; p++) { aL[p] = sb[coL]; aH[p] = sb[coH]; }
            #pragma unroll
            for (int k = 0; k < 9; k++) {
                int ky = k / 3, kx = k - ky * 3;
                float wl = sw[coL * 9 + k], wh = sw[coH * 9 + k];
                #pragma unroll
                for (int p = 0; p < 4; p++) {
                    aL[p] = fmaf(inp[ky][p + kx], wl, aL[p]);
                    aH[p] = fmaf(inp[ky][p + kx], wh, aH[p]);
                }
            }
            int s = slot_of(c);
            #pragma unroll
            for (int p = 0; p < 4; p++)
                rec[p][s] = pack_h2(fmaxf(aL[p], 0.0f), fmaxf(aH[p], 0.0f));
        }
        #pragma unroll
        for (int p = 0; p < 4; p++) {
            size_t base = (((size_t)(b * 4 + blk)) * 65536 + (size_t)y * 256 + x4 + p) * 8;
            *(uint4*)(out + base)     = make_uint4(rec[p][0], rec[p][1], rec[p][2], rec[p][3]);
            *(uint4*)(out + base + 4) = make_uint4(rec[p][4], rec[p][5], rec[p][6], rec[p][7]);
        }
    }
}

// ---------------- weight pre-pack: fp16 m16n8k16 A-fragments ----------------
__global__ void pack_w_kernel(const float* __restrict__ w, unsigned* __restrict__ dst,
                              int Cin, int Cout) {
    int steps = Cin >> 4;
    int total = (Cout / 64) * steps * 4608;
    for (int idx = blockIdx.x * blockDim.x + threadIdx.x; idx < total;
         idx += gridDim.x * blockDim.x) {
        int reg = idx & 3;
        int k4  = (idx >> 2) & 3;
        int q   = (idx >> 4) & 7;
        int f   = (idx >> 7) & 1;
        int mw  = (idx >> 8) & 1;
        int tap = (idx >> 9) % 9;
        int rest = idx / 4608;
        int step = rest % steps;
        int cb   = rest / steps;
        int co = cb * 64 + mw * 32 + f * 16 + q + (reg & 1) * 8;
        int c  = k4 + (reg >> 1) * 4;
        int ci_lo = step * 16 + c;
        float lo = w[((size_t)co * Cin + ci_lo) * 9 + tap];
        float hi = w[((size_t)co * Cin + ci_lo + 8) * 9 + tap];
        dst[idx] = pack_h2(lo, hi);
    }
}

// ---------------- tensor-core 3x3 SAME conv (fp16 m16n8k16) ----------------
// 512 threads = 16 warps (2 M x 8 N), 512-px tiles (full width), 64 co/CTA,
// K=16/step, 3-stage cp.async ring, one __syncthreads per step.
// mode 0: store ; 1: diff-reduce vs ref ; 2: fused 2x2 maxpool out (W=256).
template<int W>
__global__ __launch_bounds__(512, 1) void conv_mma(
    const unsigned* __restrict__ in, const unsigned* __restrict__ wpack,
    const float* __restrict__ bias,
    unsigned* __restrict__ out, const unsigned* __restrict__ ref,
    int Cin, int Cout, int mode)
{
    constexpr int H = W;
    constexpr int HW = W * W;
    constexpr int LW = (W == 256) ? 8 : 7;
    constexpr int TROWS = 512 / W;           // 2 (W=256) or 4 (W=128)
    constexpr int SROWS = TROWS + 2;
    constexpr int SCOLS = W + 2;
    constexpr int NREC  = SROWS * SCOLS;     // 1032 / 780
    constexpr int SIN_U = NREC * 8;          // 8256 / 6240
    constexpr int SW_U  = 9 * 512;           // 4608

    extern __shared__ unsigned smem_u[];
    unsigned* s_in = smem_u;                 // 3 buffers
    unsigned* s_w  = smem_u + 3 * SIN_U;     // 3 buffers
    __shared__ float s_red[32];

    int tid = threadIdx.x;
    int warp = tid >> 5;
    int lane = tid & 31;
    int q  = lane >> 2;
    int k4 = lane & 3;
    int mw = warp & 1;
    int nw = warp >> 1;                      // 0..7
    int mwoff = mw * 32;
    int nwoff = nw * 64;

    int y0 = blockIdx.x * TROWS;
    int cb  = blockIdx.y;
    int co0 = cb * 64;
    int b   = blockIdx.z;
    int steps = Cin >> 4;

    unsigned s_in_u = (unsigned)__cvta_generic_to_shared(s_in);
    unsigned s_w_u  = (unsigned)__cvta_generic_to_shared(s_w);

    int awb0 = ((mw * 2 + 0) * 8 + q) * 16 + k4 * 4;
    int awb1 = awb0 + 128;

    int bb[8];
    #pragma unroll
    for (int nf = 0; nf < 8; nf++) {
        int base = nwoff + nf * 8;
        int ry   = base >> LW;
        int col  = base & (W - 1);
        bb[nf] = ((ry * SCOLS + col) + q) * 8 + 2 * k4;
    }

    float acc[2][8][4];
    #pragma unroll
    for (int f = 0; f < 2; f++)
        #pragma unroll
        for (int nf = 0; nf < 8; nf++)
            #pragma unroll
            for (int e = 0; e < 4; e++) acc[f][nf][e] = 0.0f;

    const unsigned* inb = in + (size_t)b * (Cin >> 4) * HW * 8;
    const unsigned* wblk = wpack + (size_t)cb * steps * 4608;

    auto stage = [&](int step, int buf) {
        const unsigned* pbase = inb + (size_t)step * HW * 8;
        unsigned ibase = s_in_u + buf * SIN_U * 4;
        for (int i = tid; i < NREC * 2; i += 512) {
            int p = i >> 1;
            int half = i & 1;
            int r = p / SCOLS, cc = p - r * SCOLS;
            int gy = y0 - 1 + r;
            int gx = cc - 1;
            bool ok = ((unsigned)gy < (unsigned)H) && ((unsigned)gx < (unsigned)W);
            const unsigned* src = pbase + (size_t)(ok ? (gy * W + gx) : 0) * 8 + half * 4;
            cp_async16z(ibase + (unsigned)(p * 8 + half * 4) * 4, src, ok);
        }
        unsigned wbase = s_w_u + buf * SW_U * 4;
        const unsigned* wsrc = wblk + (size_t)step * 4608;
        for (int i = tid; i < 1152; i += 512)
            cp_async16(wbase + (unsigned)i * 16, wsrc + i * 4);
    };

    stage(0, 0);
    cp_commit();
    if (steps > 1) { stage(1, 1); cp_commit(); }

    int buf = 0;
    for (int s = 0; s < steps; s++) {
        if (s + 1 < steps) { cp_wait<1>(); } else { cp_wait<0>(); }
        __syncthreads();
        if (s + 2 < steps) {
            int nbuf = buf + 2; if (nbuf >= 3) nbuf -= 3;
            stage(s + 2, nbuf);
            cp_commit();
        }

        const unsigned* bin = s_in + buf * SIN_U;
        const unsigned* bw  = s_w  + buf * SW_U;

        #pragma unroll
        for (int tap = 0; tap < 9; tap++) {
            const int ky = tap / 3, kx = tap - ky * 3;
            const int toff = (ky * SCOLS + kx) * 8;
            uint4 af0 = *(const uint4*)(bw + tap * 512 + awb0);
            uint4 af1 = *(const uint4*)(bw + tap * 512 + awb1);
            #pragma unroll
            for (int nf = 0; nf < 8; nf++) {
                uint2 bv = *(const uint2*)(bin + bb[nf] + toff);
                mma_f16(acc[0][nf], af0, bv);
                mma_f16(acc[1][nf], af1, bv);
            }
        }
        buf++; if (buf >= 3) buf = 0;
    }

    // ---- epilogue ----
    int sl = slot_of(q);
    if (mode == 0) {
        #pragma unroll
        for (int f = 0; f < 2; f++) {
            int coL = co0 + mwoff + f * 16 + q;
            float bv0 = __ldg(&bias[coL]);
            float bv8 = __ldg(&bias[coL + 8]);
            int plane = (co0 + mwoff + f * 16) >> 4;
            unsigned* pl = out + ((size_t)b * (Cout >> 4) + plane) * HW * 8;
            #pragma unroll
            for (int nf = 0; nf < 8; nf++) {
                int n = nwoff + nf * 8 + 2 * k4;
                int idx = (y0 + (n >> LW)) * W + (n & (W - 1));
                pl[(size_t)idx * 8 + sl] =
                    pack_h2(fmaxf(acc[f][nf][0] + bv0, 0.0f),
                            fmaxf(acc[f][nf][2] + bv8, 0.0f));
                pl[(size_t)(idx + 1) * 8 + sl] =
                    pack_h2(fmaxf(acc[f][nf][1] + bv0, 0.0f),
                            fmaxf(acc[f][nf][3] + bv8, 0.0f));
            }
        }
    } else if (mode == 1) {
        float lsum = 0.0f;
        #pragma unroll
        for (int f = 0; f < 2; f++) {
            int coL = co0 + mwoff + f * 16 + q;
            float bv0 = __ldg(&bias[coL]);
            float bv8 = __ldg(&bias[coL + 8]);
            int plane = (co0 + mwoff + f * 16) >> 4;
            const unsigned* pl = ref + ((size_t)b * (Cout >> 4) + plane) * HW * 8;
            #pragma unroll
            for (int nf = 0; nf < 8; nf++) {
                int n = nwoff + nf * 8 + 2 * k4;
                int idx = (y0 + (n >> LW)) * W + (n & (W - 1));
                float2 r0 = unpack_h2(pl[(size_t)idx * 8 + sl]);
                float2 r1 = unpack_h2(pl[(size_t)(idx + 1) * 8 + sl]);
                float d0 = h16r(fmaxf(acc[f][nf][0] + bv0, 0.0f)) - r0.x;
                float d1 = h16r(fmaxf(acc[f][nf][2] + bv8, 0.0f)) - r0.y;
                float d2 = h16r(fmaxf(acc[f][nf][1] + bv0, 0.0f)) - r1.x;
                float d3 = h16r(fmaxf(acc[f][nf][3] + bv8, 0.0f)) - r1.y;
                lsum = fmaf(d0, d0, lsum);
                lsum = fmaf(d1, d1, lsum);
                lsum = fmaf(d2, d2, lsum);
                lsum = fmaf(d3, d3, lsum);
            }
        }
        float tot = block_reduce_sum512(lsum, s_red, tid);
        if (tid == 0) atomicAdd(&g_acc[2], (double)tot);
    } else {
        // mode 2 (W=256): fused 2x2 maxpool. Tile = 2 rows x 256 cols.
        // spool[(row*256 + x)*32 + lp], 16384 u32 <= 3*SIN_U.
        __syncthreads();
        unsigned* spool = s_in;
        #pragma unroll
        for (int f = 0; f < 2; f++) {
            int coL = co0 + mwoff + f * 16 + q;
            float bv0 = __ldg(&bias[coL]);
            float bv8 = __ldg(&bias[coL + 8]);
            int lp = ((mwoff + f * 16) >> 4) * 8 + q;
            #pragma unroll
            for (int nf = 0; nf < 8; nf++) {
                int n = nwoff + nf * 8 + 2 * k4;
                int row = n >> 8, x = n & 255;
                spool[(row * 256 + x) * 32 + lp] =
                    pack_h2(fmaxf(acc[f][nf][0] + bv0, 0.0f),
                            fmaxf(acc[f][nf][2] + bv8, 0.0f));
                spool[(row * 256 + x + 1) * 32 + lp] =
                    pack_h2(fmaxf(acc[f][nf][1] + bv0, 0.0f),
                            fmaxf(acc[f][nf][3] + bv8, 0.0f));
            }
        }
        __syncthreads();
        int prow = blockIdx.x;                 // pooled row (y0 = 2*blockIdx.x)
        for (int i = tid; i < 4096; i += 512) {
            int X  = i & 127;
            int lp = i >> 7;
            unsigned m = hm2(hm2(spool[(2 * X) * 32 + lp],
                                 spool[(2 * X + 1) * 32 + lp]),
                             hm2(spool[(256 + 2 * X) * 32 + lp],
                                 spool[(257 + 2 * X) * 32 + lp]));
            int pl_loc = lp >> 3, c = lp & 7;
            out[(((size_t)b * 8 + cb * 4 + pl_loc) * 16384
                 + (size_t)(prow * 128 + X)) * 8 + slot_of(c)] = m;
        }
    }
}

// ---------------- finalize ----------------
__global__ void finalize_kernel(float* out, int out_size) {
    double mse    = g_acc[0] / 524288.0;
    double ssim_l = 1.0 - g_acc[1] / 500000.0;
    double perc   = g_acc[2] / 33554432.0;
    double total  = mse + 0.5 * ssim_l + 0.1 * perc;
    float vals[4] = {(float)total, (float)mse, (float)ssim_l, (float)perc};
    for (int i = 0; i < 4 && i < out_size; i++) out[i] = vals[i];
}

// ---------------- launcher ----------------
extern "C" void kernel_launch(void* const* d_in, const int* in_sizes, int n_in,
                              void* d_out, int out_size) {
    (void)in_sizes; (void)n_in;
    const float* sr = (const float*)d_in[0];
    const float* hr = (const float*)d_in[1];
    const float* w1 = (const float*)d_in[2];
    const float* b1 = (const float*)d_in[3];
    const float* w2 = (const float*)d_in[4];
    const float* b2 = (const float*)d_in[5];
    const float* w3 = (const float*)d_in[6];
    const float* b3 = (const float*)d_in[7];
    const float* w4 = (const float*)d_in[8];
    const float* b4 = (const float*)d_in[9];
    float* out = (float*)d_out;

    unsigned *A, *P, *C, *D, *WP;
    cudaGetSymbolAddress((void**)&A, g_bufA);
    cudaGetSymbolAddress((void**)&P, g_bufP);
    cudaGetSymbolAddress((void**)&C, g_bufC);
    cudaGetSymbolAddress((void**)&D, g_bufD);
    cudaGetSymbolAddress((void**)&WP, g_wpk);
    unsigned* WP2 = WP;             // 36864 u32
    unsigned* WP3 = WP + 36864;     // 147456 u32
    unsigned* WP4 = WP + 184320;    // 294912 u32

    const int smem256 = (3 * 8256 + 3 * 4608) * 4;   // 154368 B
    const int smem128 = (3 * 6240 + 3 * 4608) * 4;   // 130176 B
    cudaFuncSetAttribute(conv_mma<256>, cudaFuncAttributeMaxDynamicSharedMemorySize, smem256);
    cudaFuncSetAttribute(conv_mma<128>, cudaFuncAttributeMaxDynamicSharedMemorySize, smem128);

    zero_acc_kernel<<<1, 1>>>();
    pack_w_kernel<<<144, 256>>>(w2, WP2, 64, 128);
    conv1_kernel<<<512, 256>>>(sr, w1, b1, A);
    conv_mma<256><<<dim3(128, 2, 8), 512, smem256>>>(A, WP2, b2, P, nullptr, 64, 128, 2);
    pack_w_kernel<<<576, 256>>>(w3, WP3, 128, 256);
    conv_mma<128><<<dim3(32, 4, 8), 512, smem128>>>(P, WP3, b3, C, nullptr, 128, 256, 0);
    pack_w_kernel<<<1152, 256>>>(w4, WP4, 256, 256);
    conv_mma<128><<<dim3(32, 4, 8), 512, smem128>>>(C, WP4, b4, D, nullptr, 256, 256, 0);
    mse_kernel<<<512, 256>>>(sr, hr, 524288);
    ssim_kernel<<<dim3(16, 16, 8), dim3(16, 16)>>>(sr, hr);

    // hr pass
    conv1_kernel<<<512, 256>>>(hr, w1, b1, A);
    conv_mma<256><<<dim3(128, 2, 8), 512, smem256>>>(A, WP2, b2, P, nullptr, 64, 128, 2);
    conv_mma<128><<<dim3(32, 4, 8), 512, smem128>>>(P, WP3, b3, C, nullptr, 128, 256, 0);
    conv_mma<128><<<dim3(32, 4, 8), 512, smem128>>>(C, WP4, b4, nullptr, D, 256, 256, 1);

    finalize_kernel<<<1, 1>>>(out, out_size);
}

// round 14
// speedup vs baseline: 1.0341x; 1.0341x over previous
#include <cuda_runtime.h>
#include <cuda_fp16.h>
#include <cstdint>

// ---------------- scratch (device globals; no allocation allowed) ----------
// Activations: [b][plane=16ch][HW px][8 u32 record], record = slot-permuted
// fp16x2 pairs: slot(c) = (c&3)*2+(c>>2) holds channels (c, c+8), c=0..7.
__device__ unsigned g_bufA[16777216];  // conv1 out (8,4pl,65536,8)
__device__ unsigned g_bufP[8388608];   // pooled    (8,8pl,16384,8)
__device__ unsigned g_bufC[16777216];  // conv3 out (8,16pl,16384,8)
__device__ unsigned g_bufD[16777216];  // conv4 out sr pass
__device__ unsigned g_wpk[524288];     // packed fp16 A-fragment weights
__device__ double g_acc[3];            // 0: mse, 1: ssim, 2: perceptual

__global__ void zero_acc_kernel() { g_acc[0]=0.0; g_acc[1]=0.0; g_acc[2]=0.0; }

// ---------------- helpers ----------------
__device__ __forceinline__ float block_reduce_sum256(float v, float* sh, int tid) {
    #pragma unroll
    for (int o = 16; o > 0; o >>= 1) v += __shfl_down_sync(0xffffffffu, v, o);
    if ((tid & 31) == 0) sh[tid >> 5] = v;
    __syncthreads();
    if (tid < 32) {
        v = (tid < 8) ? sh[tid] : 0.0f;
        #pragma unroll
        for (int o = 4; o > 0; o >>= 1) v += __shfl_down_sync(0xffffffffu, v, o);
    }
    return v;
}
__device__ __forceinline__ unsigned pack_h2(float lo, float hi) {
    __half2 h = __floats2half2_rn(lo, hi);
    return *(unsigned*)&h;
}
__device__ __forceinline__ float2 unpack_h2(unsigned u) {
    __half2 h = *(__half2*)&u;
    return __half22float2(h);
}
__device__ __forceinline__ float h16r(float x) {
    return __half2float(__float2half_rn(x));
}
__device__ __forceinline__ unsigned hm2(unsigned a, unsigned b) {
    __half2 r = __hmax2(*(__half2*)&a, *(__half2*)&b);
    return *(unsigned*)&r;
}
__device__ __forceinline__ void mma_f16(float* c, const uint4 a, const uint2 b) {
    asm volatile(
        "mma.sync.aligned.m16n8k16.row.col.f32.f16.f16.f32 "
        "{%0,%1,%2,%3}, {%4,%5,%6,%7}, {%8,%9}, {%0,%1,%2,%3};"
        : "+f"(c[0]), "+f"(c[1]), "+f"(c[2]), "+f"(c[3])
        : "r"(a.x), "r"(a.y), "r"(a.z), "r"(a.w), "r"(b.x), "r"(b.y));
}
__device__ __forceinline__ void cp_async16(unsigned dst, const void* src) {
    asm volatile("cp.async.cg.shared.global [%0], [%1], 16;" :: "r"(dst), "l"(src));
}
__device__ __forceinline__ void cp_async16z(unsigned dst, const void* src, bool ok) {
    int sz = ok ? 16 : 0;
    asm volatile("cp.async.cg.shared.global [%0], [%1], 16, %2;"
                 :: "r"(dst), "l"(src), "r"(sz));
}
__device__ __forceinline__ void cp_commit() { asm volatile("cp.async.commit_group;"); }
template<int N> __device__ __forceinline__ void cp_wait() {
    asm volatile("cp.async.wait_group %0;" :: "n"(N));
}
__device__ __forceinline__ int slot_of(int c) { return ((c & 3) << 1) + (c >> 2); }

// ---------------- SSIM + fused MSE ----------------
__global__ void ssim_kernel(const float* __restrict__ x, const float* __restrict__ y) {
    __shared__ float sxt[22][23];
    __shared__ float syt[22][23];
    __shared__ float sh[32];
    int b = blockIdx.z;
    int gx0 = blockIdx.x * 16, gy0 = blockIdx.y * 16;
    const float* xb = x + (size_t)b * 65536;
    const float* yb = y + (size_t)b * 65536;
    int tid = threadIdx.y * 16 + threadIdx.x;
    for (int i = tid; i < 22 * 22; i += 256) {
        int rr = i / 22, cc = i - rr * 22;
        int gy = gy0 + rr, gx = gx0 + cc;
        float vx = 0.0f, vy = 0.0f;
        if (gy < 256 && gx < 256) { vx = xb[gy * 256 + gx]; vy = yb[gy * 256 + gx]; }
        sxt[rr][cc] = vx; syt[rr][cc] = vy;
    }
    __syncthreads();
    int i = gy0 + threadIdx.y, j = gx0 + threadIdx.x;
    float S = 0.0f;
    if (i < 250 && j < 250) {
        float sx = 0, sy = 0, sxx = 0, syy = 0, sxy = 0;
        #pragma unroll
        for (int dy = 0; dy < 7; dy++)
            #pragma unroll
            for (int dx = 0; dx < 7; dx++) {
                float a = sxt[threadIdx.y + dy][threadIdx.x + dx];
                float c = syt[threadIdx.y + dy][threadIdx.x + dx];
                sx += a; sy += c;
                sxx = fmaf(a, a, sxx); syy = fmaf(c, c, syy); sxy = fmaf(a, c, sxy);
            }
        const float inv = 1.0f / 49.0f, cn = 49.0f / 48.0f;
        float ux = sx * inv, uy = sy * inv;
        float vx  = cn * (sxx * inv - ux * ux);
        float vy  = cn * (syy * inv - uy * uy);
        float vxy = cn * (sxy * inv - ux * uy);
        const float C1 = 1e-4f, C2 = 9e-4f;
        S = ((2.0f * ux * uy + C1) * (2.0f * vxy + C2)) /
            ((ux * ux + uy * uy + C1) * (vx + vy + C2));
    }
    // fused MSE: owned pixel (gy0+ty, gx0+tx) counted exactly once per image
    float dmse = sxt[threadIdx.y][threadIdx.x] - syt[threadIdx.y][threadIdx.x];
    float msq = dmse * dmse;

    float totS = block_reduce_sum256(S, sh, tid);
    if (tid == 0) atomicAdd(&g_acc[1], (double)totS);
    __syncthreads();
    float totM = block_reduce_sum256(msq, sh, tid);
    if (tid == 0) atomicAdd(&g_acc[0], (double)totM);
}

// ---------------- conv1: 1 -> 64 ch, relu, 32B pixel records ----------
__global__ void conv1_kernel(const float* __restrict__ in, const float* __restrict__ w,
                             const float* __restrict__ bias, unsigned* __restrict__ out) {
    __shared__ float sw[576];
    __shared__ float sb[64];
    int tid = threadIdx.x;
    for (int i = tid; i < 576; i += 256) sw[i] = w[i];
    if (tid < 64) sb[tid] = bias[tid];
    __syncthreads();
    int g = blockIdx.x * 256 + tid;
    int x4 = (g & 63) * 4;
    int y  = (g >> 6) & 255;
    int b  = g >> 14;
    const float* ib = in + (size_t)b * 65536;
    float inp[3][6];
    #pragma unroll
    for (int dy = 0; dy < 3; dy++) {
        int gy = y - 1 + dy;
        #pragma unroll
        for (int c = 0; c < 6; c++) {
            int gx = x4 - 1 + c;
            inp[dy][c] = ((unsigned)gy < 256u && (unsigned)gx < 256u) ? ib[gy * 256 + gx] : 0.0f;
        }
    }
    for (int blk = 0; blk < 4; blk++) {
        unsigned rec[4][8];
        for (int c = 0; c < 8; c++) {
            int coL = 16 * blk + c, coH = coL + 8;
            float aL[4], aH[4];
            #pragma unroll
            for (int p = 0; p < 4; p++) { aL[p] = sb[coL]; aH[p] = sb[coH]; }
            #pragma unroll
            for (int k = 0; k < 9; k++) {
                int ky = k / 3, kx = k - ky * 3;
                float wl = sw[coL * 9 + k], wh = sw[coH * 9 + k];
                #pragma unroll
                for (int p = 0; p < 4; p++) {
                    aL[p] = fmaf(inp[ky][p + kx], wl, aL[p]);
                    aH[p] = fmaf(inp[ky][p + kx], wh, aH[p]);
                }
            }
            int s = slot_of(c);
            #pragma unroll
            for (int p = 0; p < 4; p++)
                rec[p][s] = pack_h2(fmaxf(aL[p], 0.0f), fmaxf(aH[p], 0.0f));
        }
        #pragma unroll
        for (int p = 0; p < 4; p++) {
            size_t base = (((size_t)(b * 4 + blk)) * 65536 + (size_t)y * 256 + x4 + p) * 8;
            *(uint4*)(out + base)     = make_uint4(rec[p][0], rec[p][1], rec[p][2], rec[p][3]);
            *(uint4*)(out + base + 4) = make_uint4(rec[p][4], rec[p][5], rec[p][6], rec[p][7]);
        }
    }
}

// ---------------- weight pre-pack: fp16 m16n8k16 A-fragments ----------------
__global__ void pack_w_kernel(const float* __restrict__ w, unsigned* __restrict__ dst,
                              int Cin, int Cout) {
    int steps = Cin >> 4;
    int total = (Cout / 64) * steps * 4608;
    for (int idx = blockIdx.x * blockDim.x + threadIdx.x; idx < total;
         idx += gridDim.x * blockDim.x) {
        int reg = idx & 3;
        int k4  = (idx >> 2) & 3;
        int q   = (idx >> 4) & 7;
        int f   = (idx >> 7) & 1;
        int mw  = (idx >> 8) & 1;
        int tap = (idx >> 9) % 9;
        int rest = idx / 4608;
        int step = rest % steps;
        int cb   = rest / steps;
        int co = cb * 64 + mw * 32 + f * 16 + q + (reg & 1) * 8;
        int c  = k4 + (reg >> 1) * 4;
        int ci_lo = step * 16 + c;
        float lo = w[((size_t)co * Cin + ci_lo) * 9 + tap];
        float hi = w[((size_t)co * Cin + ci_lo + 8) * 9 + tap];
        dst[idx] = pack_h2(lo, hi);
    }
}

// ---------------- tensor-core 3x3 SAME conv (fp16 m16n8k16) ----------------
// 256 threads = 8 warps (2M x 4N), 128x2 strip tiles, 64 co/CTA, K=16/step.
// PRE=true : all weights preloaded to SMEM, 2-buffer input ring (conv2).
// PRE=false: 3-stage ring for inputs+weights, one sync/step (conv3/4).
// mode 0: store ; 1: diff-reduce vs ref ; 2: fused 2x2 maxpool out.
template<int W, bool PRE>
__global__ __launch_bounds__(256, 2) void conv_mma(
    const unsigned* __restrict__ in, const unsigned* __restrict__ wpack,
    const float* __restrict__ bias,
    unsigned* __restrict__ out, const unsigned* __restrict__ ref,
    int Cin, int Cout, int mode)
{
    constexpr int H = W;
    constexpr int HW = W * W;
    constexpr int SCOLS = 130;
    constexpr int NPIX  = 4 * SCOLS;         // 520
    constexpr int SIN_U = NPIX * 8;          // 4160
    constexpr int SW_U  = 9 * 512;           // 4608
    constexpr int STRIPS = W >> 7;
    constexpr int NIN = PRE ? 2 : 3;

    extern __shared__ unsigned smem_u[];
    unsigned* s_in = smem_u;                 // NIN buffers
    unsigned* s_w  = smem_u + NIN * SIN_U;   // PRE: steps bufs ; else 3 bufs
    __shared__ float s_red[32];

    int tid = threadIdx.x;
    int warp = tid >> 5;
    int lane = tid & 31;
    int q  = lane >> 2;
    int k4 = lane & 3;
    int mw = warp & 1;
    int nw = warp >> 1;
    int mwoff = mw * 32;
    int nwoff = nw * 64;

    int strip = blockIdx.x % STRIPS;
    int ypair = blockIdx.x / STRIPS;
    int y0 = ypair * 2;
    int c0 = strip << 7;
    int cb  = blockIdx.y;
    int co0 = cb * 64;
    int b   = blockIdx.z;
    int steps = Cin >> 4;

    unsigned s_in_u = (unsigned)__cvta_generic_to_shared(s_in);
    unsigned s_w_u  = (unsigned)__cvta_generic_to_shared(s_w);

    int awb0 = ((mw * 2 + 0) * 8 + q) * 16 + k4 * 4;
    int awb1 = awb0 + 128;

    int bb[8];
    #pragma unroll
    for (int nf = 0; nf < 8; nf++) {
        int base = nwoff + nf * 8;
        int ry   = base >> 7;
        int col  = base & 127;
        bb[nf] = ((ry * SCOLS + col) + q) * 8 + 2 * k4;
    }

    float acc[2][8][4];
    #pragma unroll
    for (int f = 0; f < 2; f++)
        #pragma unroll
        for (int nf = 0; nf < 8; nf++)
            #pragma unroll
            for (int e = 0; e < 4; e++) acc[f][nf][e] = 0.0f;

    const unsigned* inb = in + (size_t)b * (Cin >> 4) * HW * 8;
    const unsigned* wblk = wpack + (size_t)cb * steps * 4608;

    auto stageI = [&](int step, int buf) {
        const unsigned* pbase = inb + (size_t)step * HW * 8;
        unsigned ibase = s_in_u + buf * SIN_U * 4;
        #pragma unroll 4
        for (int i = tid; i < NPIX * 2; i += 256) {
            int p = i >> 1;
            int half = i & 1;
            int r = p / SCOLS, cc = p - r * SCOLS;
            int gy = y0 - 1 + r;
            int gx = c0 + cc - 1;
            bool ok = ((unsigned)gy < (unsigned)H) && ((unsigned)gx < (unsigned)W);
            const unsigned* src = pbase + (size_t)(ok ? (gy * W + gx) : 0) * 8 + half * 4;
            cp_async16z(ibase + (unsigned)(p * 8 + half * 4) * 4, src, ok);
        }
    };
    auto stageW = [&](int step, int buf) {
        unsigned wbase = s_w_u + buf * SW_U * 4;
        const unsigned* wsrc = wblk + (size_t)step * 4608;
        #pragma unroll
        for (int i = tid; i < 1152; i += 256)
            cp_async16(wbase + (unsigned)i * 16, wsrc + i * 4);
    };

    if (PRE) {
        // All weights resident; 2-buffer input ring, two syncs/step.
        for (int s = 0; s < steps; s++) stageW(s, s);
        stageI(0, 0);
        cp_commit();
        if (steps > 1) { stageI(1, 1); cp_commit(); }

        for (int s = 0; s < steps; s++) {
            if (s + 1 < steps) { cp_wait<1>(); } else { cp_wait<0>(); }
            __syncthreads();
            const unsigned* bin = s_in + (s & 1) * SIN_U;
            const unsigned* bw  = s_w + s * SW_U;
            #pragma unroll
            for (int tap = 0; tap < 9; tap++) {
                const int ky = tap / 3, kx = tap - ky * 3;
                const int toff = (ky * SCOLS + kx) * 8;
                uint4 af0 = *(const uint4*)(bw + tap * 512 + awb0);
                uint4 af1 = *(const uint4*)(bw + tap * 512 + awb1);
                #pragma unroll
                for (int nf = 0; nf < 8; nf++) {
                    uint2 bv = *(const uint2*)(bin + bb[nf] + toff);
                    mma_f16(acc[0][nf], af0, bv);
                    mma_f16(acc[1][nf], af1, bv);
                }
            }
            __syncthreads();
            if (s + 2 < steps) { stageI(s + 2, s & 1); cp_commit(); }
        }
    } else {
        // 3-stage ring for inputs+weights, one sync/step.
        stageI(0, 0); stageW(0, 0);
        cp_commit();
        if (steps > 1) { stageI(1, 1); stageW(1, 1); cp_commit(); }

        int buf = 0;
        for (int s = 0; s < steps; s++) {
            if (s + 1 < steps) { cp_wait<1>(); } else { cp_wait<0>(); }
            __syncthreads();
            if (s + 2 < steps) {
                int nbuf = buf + 2; if (nbuf >= 3) nbuf -= 3;
                stageI(s + 2, nbuf); stageW(s + 2, nbuf);
                cp_commit();
            }
            const unsigned* bin = s_in + buf * SIN_U;
            const unsigned* bw  = s_w  + buf * SW_U;
            #pragma unroll
            for (int tap = 0; tap < 9; tap++) {
                const int ky = tap / 3, kx = tap - ky * 3;
                const int toff = (ky * SCOLS + kx) * 8;
                uint4 af0 = *(const uint4*)(bw + tap * 512 + awb0);
                uint4 af1 = *(const uint4*)(bw + tap * 512 + awb1);
                #pragma unroll
                for (int nf = 0; nf < 8; nf++) {
                    uint2 bv = *(const uint2*)(bin + bb[nf] + toff);
                    mma_f16(acc[0][nf], af0, bv);
                    mma_f16(acc[1][nf], af1, bv);
                }
            }
            buf++; if (buf >= 3) buf = 0;
        }
    }

    // ---- epilogue ----
    int sl = slot_of(q);
    if (mode == 0) {
        #pragma unroll
        for (int f = 0; f < 2; f++) {
            int coL = co0 + mwoff + f * 16 + q;
            float bv0 = __ldg(&bias[coL]);
            float bv8 = __ldg(&bias[coL + 8]);
            int plane = (co0 + mwoff + f * 16) >> 4;
            unsigned* pl = out + ((size_t)b * (Cout >> 4) + plane) * HW * 8;
            #pragma unroll
            for (int nf = 0; nf < 8; nf++) {
                int n = nwoff + nf * 8 + 2 * k4;
                int idx = (y0 + (n >> 7)) * W + c0 + (n & 127);
                pl[(size_t)idx * 8 + sl] =
                    pack_h2(fmaxf(acc[f][nf][0] + bv0, 0.0f),
                            fmaxf(acc[f][nf][2] + bv8, 0.0f));
                pl[(size_t)(idx + 1) * 8 + sl] =
                    pack_h2(fmaxf(acc[f][nf][1] + bv0, 0.0f),
                            fmaxf(acc[f][nf][3] + bv8, 0.0f));
            }
        }
    } else if (mode == 1) {
        float lsum = 0.0f;
        #pragma unroll
        for (int f = 0; f < 2; f++) {
            int coL = co0 + mwoff + f * 16 + q;
            float bv0 = __ldg(&bias[coL]);
            float bv8 = __ldg(&bias[coL + 8]);
            int plane = (co0 + mwoff + f * 16) >> 4;
            const unsigned* pl = ref + ((size_t)b * (Cout >> 4) + plane) * HW * 8;
            #pragma unroll
            for (int nf = 0; nf < 8; nf++) {
                int n = nwoff + nf * 8 + 2 * k4;
                int idx = (y0 + (n >> 7)) * W + c0 + (n & 127);
                float2 r0 = unpack_h2(pl[(size_t)idx * 8 + sl]);
                float2 r1 = unpack_h2(pl[(size_t)(idx + 1) * 8 + sl]);
                float d0 = h16r(fmaxf(acc[f][nf][0] + bv0, 0.0f)) - r0.x;
                float d1 = h16r(fmaxf(acc[f][nf][2] + bv8, 0.0f)) - r0.y;
                float d2 = h16r(fmaxf(acc[f][nf][1] + bv0, 0.0f)) - r1.x;
                float d3 = h16r(fmaxf(acc[f][nf][3] + bv8, 0.0f)) - r1.y;
                lsum = fmaf(d0, d0, lsum);
                lsum = fmaf(d1, d1, lsum);
                lsum = fmaf(d2, d2, lsum);
                lsum = fmaf(d3, d3, lsum);
            }
        }
        float tot = block_reduce_sum256(lsum, s_red, tid);
        if (tid == 0) atomicAdd(&g_acc[2], (double)tot);
    } else {
        // mode 2: fused 2x2 maxpool (conv2, W=256). spool[(row*128+x)*32 + lp]
        __syncthreads();
        unsigned* spool = s_in;   // 8192 u32 <= 2*SIN_U
        #pragma unroll
        for (int f = 0; f < 2; f++) {
            int coL = co0 + mwoff + f * 16 + q;
            float bv0 = __ldg(&bias[coL]);
            float bv8 = __ldg(&bias[coL + 8]);
            int lp = ((mwoff + f * 16) >> 4) * 8 + q;
            #pragma unroll
            for (int nf = 0; nf < 8; nf++) {
                int n = nwoff + nf * 8 + 2 * k4;
                int row = n >> 7, x = n & 127;
                spool[(row * 128 + x) * 32 + lp] =
                    pack_h2(fmaxf(acc[f][nf][0] + bv0, 0.0f),
                            fmaxf(acc[f][nf][2] + bv8, 0.0f));
                spool[(row * 128 + x + 1) * 32 + lp] =
                    pack_h2(fmaxf(acc[f][nf][1] + bv0, 0.0f),
                            fmaxf(acc[f][nf][3] + bv8, 0.0f));
            }
        }
        __syncthreads();
        int ypix = ypair * 128 + (c0 >> 1);
        for (int i = tid; i < 2048; i += 256) {
            int lp = i >> 6;
            int X  = i & 63;
            unsigned m = hm2(hm2(spool[(2 * X) * 32 + lp],
                                 spool[(2 * X + 1) * 32 + lp]),
                             hm2(spool[(128 + 2 * X) * 32 + lp],
                                 spool[(129 + 2 * X) * 32 + lp]));
            int pl_loc = lp >> 3, c = lp & 7;
            out[(((size_t)b * 8 + cb * 4 + pl_loc) * 16384
                 + (size_t)(ypix + X)) * 8 + slot_of(c)] = m;
        }
    }
}

// ---------------- finalize ----------------
__global__ void finalize_kernel(float* out, int out_size) {
    double mse    = g_acc[0] / 524288.0;
    double ssim_l = 1.0 - g_acc[1] / 500000.0;
    double perc   = g_acc[2] / 33554432.0;
    double total  = mse + 0.5 * ssim_l + 0.1 * perc;
    float vals[4] = {(float)total, (float)mse, (float)ssim_l, (float)perc};
    for (int i = 0; i < 4 && i < out_size; i++) out[i] = vals[i];
}

// ---------------- launcher ----------------
extern "C" void kernel_launch(void* const* d_in, const int* in_sizes, int n_in,
                              void* d_out, int out_size) {
    (void)in_sizes; (void)n_in;
    const float* sr = (const float*)d_in[0];
    const float* hr = (const float*)d_in[1];
    const float* w1 = (const float*)d_in[2];
    const float* b1 = (const float*)d_in[3];
    const float* w2 = (const float*)d_in[4];
    const float* b2 = (const float*)d_in[5];
    const float* w3 = (const float*)d_in[6];
    const float* b3 = (const float*)d_in[7];
    const float* w4 = (const float*)d_in[8];
    const float* b4 = (const float*)d_in[9];
    float* out = (float*)d_out;

    unsigned *A, *P, *C, *D, *WP;
    cudaGetSymbolAddress((void**)&A, g_bufA);
    cudaGetSymbolAddress((void**)&P, g_bufP);
    cudaGetSymbolAddress((void**)&C, g_bufC);
    cudaGetSymbolAddress((void**)&D, g_bufD);
    cudaGetSymbolAddress((void**)&WP, g_wpk);
    unsigned* WP2 = WP;             // 36864 u32
    unsigned* WP3 = WP + 36864;     // 147456 u32
    unsigned* WP4 = WP + 184320;    // 294912 u32

    const int smem2 = (2 * 4160 + 4 * 4608) * 4;   // 107008 B (conv2, PRE)
    const int smem  = (3 * 4160 + 3 * 4608) * 4;   // 105216 B (conv3/4)
    cudaFuncSetAttribute(conv_mma<256, true>,
                         cudaFuncAttributeMaxDynamicSharedMemorySize, smem2);
    cudaFuncSetAttribute(conv_mma<128, false>,
                         cudaFuncAttributeMaxDynamicSharedMemorySize, smem);

    zero_acc_kernel<<<1, 1>>>();
    pack_w_kernel<<<144, 256>>>(w2, WP2, 64, 128);
    conv1_kernel<<<512, 256>>>(sr, w1, b1, A);
    conv_mma<256, true><<<dim3(256, 2, 8), 256, smem2>>>(A, WP2, b2, P, nullptr,
                                                         64, 128, 2);
    pack_w_kernel<<<576, 256>>>(w3, WP3, 128, 256);
    conv_mma<128, false><<<dim3(64, 4, 8), 256, smem>>>(P, WP3, b3, C, nullptr,
                                                        128, 256, 0);
    pack_w_kernel<<<1152, 256>>>(w4, WP4, 256, 256);
    conv_mma<128, false><<<dim3(64, 4, 8), 256, smem>>>(C, WP4, b4, D, nullptr,
                                                        256, 256, 0);
    ssim_kernel<<<dim3(16, 16, 8), dim3(16, 16)>>>(sr, hr);   // SSIM + fused MSE

    // hr pass
    conv1_kernel<<<512, 256>>>(hr, w1, b1, A);
    conv_mma<256, true><<<dim3(256, 2, 8), 256, smem2>>>(A, WP2, b2, P, nullptr,
                                                         64, 128, 2);
    conv_mma<128, false><<<dim3(64, 4, 8), 256, smem>>>(P, WP3, b3, C, nullptr,
                                                        128, 256, 0);
    conv_mma<128, false><<<dim3(64, 4, 8), 256, smem>>>(C, WP4, b4, nullptr, D,
                                                        256, 256, 1);

    finalize_kernel<<<1, 1>>>(out, out_size);
}

// round 15
// speedup vs baseline: 1.0543x; 1.0195x over previous
#include <cuda_runtime.h>
#include <cuda_fp16.h>
#include <cstdint>

// ---------------- scratch (device globals; no allocation allowed) ----------
// Activations: [bb][plane=16ch][HW px][8 u32 record], record slot-permuted
// fp16x2 pairs: slot(c) = (c&3)*2+(c>>2) holds channels (c, c+8).
// bb = 0..7 sr images, 8..15 hr images.
__device__ unsigned g_bufA[33554432];  // conv1 out (16,4pl,65536,8)
__device__ unsigned g_bufP[16777216];  // pooled    (16,8pl,16384,8)
__device__ unsigned g_bufC[33554432];  // conv3 out (16,16pl,16384,8)
__device__ unsigned g_bufD[16777216];  // conv4 out sr pass (8,16pl,16384,8)
__device__ unsigned g_wpk[524288];     // packed fp16 A-fragment weights
__device__ double g_acc[3];            // 0: mse, 1: ssim, 2: perceptual

__global__ void zero_acc_kernel() { g_acc[0]=0.0; g_acc[1]=0.0; g_acc[2]=0.0; }

// ---------------- helpers ----------------
__device__ __forceinline__ float block_reduce_sum256(float v, float* sh, int tid) {
    #pragma unroll
    for (int o = 16; o > 0; o >>= 1) v += __shfl_down_sync(0xffffffffu, v, o);
    if ((tid & 31) == 0) sh[tid >> 5] = v;
    __syncthreads();
    if (tid < 32) {
        v = (tid < 8) ? sh[tid] : 0.0f;
        #pragma unroll
        for (int o = 4; o > 0; o >>= 1) v += __shfl_down_sync(0xffffffffu, v, o);
    }
    return v;
}
__device__ __forceinline__ unsigned pack_h2(float lo, float hi) {
    __half2 h = __floats2half2_rn(lo, hi);
    return *(unsigned*)&h;
}
__device__ __forceinline__ float2 unpack_h2(unsigned u) {
    __half2 h = *(__half2*)&u;
    return __half22float2(h);
}
__device__ __forceinline__ float h16r(float x) {
    return __half2float(__float2half_rn(x));
}
__device__ __forceinline__ unsigned hm2(unsigned a, unsigned b) {
    __half2 r = __hmax2(*(__half2*)&a, *(__half2*)&b);
    return *(unsigned*)&r;
}
__device__ __forceinline__ void mma_f16(float* c, const uint4 a, const uint2 b) {
    asm volatile(
        "mma.sync.aligned.m16n8k16.row.col.f32.f16.f16.f32 "
        "{%0,%1,%2,%3}, {%4,%5,%6,%7}, {%8,%9}, {%0,%1,%2,%3};"
        : "+f"(c[0]), "+f"(c[1]), "+f"(c[2]), "+f"(c[3])
        : "r"(a.x), "r"(a.y), "r"(a.z), "r"(a.w), "r"(b.x), "r"(b.y));
}
__device__ __forceinline__ void cp_async16(unsigned dst, const void* src) {
    asm volatile("cp.async.cg.shared.global [%0], [%1], 16;" :: "r"(dst), "l"(src));
}
__device__ __forceinline__ void cp_async16z(unsigned dst, const void* src, bool ok) {
    int sz = ok ? 16 : 0;
    asm volatile("cp.async.cg.shared.global [%0], [%1], 16, %2;"
                 :: "r"(dst), "l"(src), "r"(sz));
}
__device__ __forceinline__ void cp_commit() { asm volatile("cp.async.commit_group;"); }
template<int N> __device__ __forceinline__ void cp_wait() {
    asm volatile("cp.async.wait_group %0;" :: "n"(N));
}
__device__ __forceinline__ int slot_of(int c) { return ((c & 3) << 1) + (c >> 2); }

// ---------------- SSIM + fused MSE ----------------
__global__ void ssim_kernel(const float* __restrict__ x, const float* __restrict__ y) {
    __shared__ float sxt[22][23];
    __shared__ float syt[22][23];
    __shared__ float sh[32];
    int b = blockIdx.z;
    int gx0 = blockIdx.x * 16, gy0 = blockIdx.y * 16;
    const float* xb = x + (size_t)b * 65536;
    const float* yb = y + (size_t)b * 65536;
    int tid = threadIdx.y * 16 + threadIdx.x;
    for (int i = tid; i < 22 * 22; i += 256) {
        int rr = i / 22, cc = i - rr * 22;
        int gy = gy0 + rr, gx = gx0 + cc;
        float vx = 0.0f, vy = 0.0f;
        if (gy < 256 && gx < 256) { vx = xb[gy * 256 + gx]; vy = yb[gy * 256 + gx]; }
        sxt[rr][cc] = vx; syt[rr][cc] = vy;
    }
    __syncthreads();
    int i = gy0 + threadIdx.y, j = gx0 + threadIdx.x;
    float S = 0.0f;
    if (i < 250 && j < 250) {
        float sx = 0, sy = 0, sxx = 0, syy = 0, sxy = 0;
        #pragma unroll
        for (int dy = 0; dy < 7; dy++)
            #pragma unroll
            for (int dx = 0; dx < 7; dx++) {
                float a = sxt[threadIdx.y + dy][threadIdx.x + dx];
                float c = syt[threadIdx.y + dy][threadIdx.x + dx];
                sx += a; sy += c;
                sxx = fmaf(a, a, sxx); syy = fmaf(c, c, syy); sxy = fmaf(a, c, sxy);
            }
        const float inv = 1.0f / 49.0f, cn = 49.0f / 48.0f;
        float ux = sx * inv, uy = sy * inv;
        float vx  = cn * (sxx * inv - ux * ux);
        float vy  = cn * (syy * inv - uy * uy);
        float vxy = cn * (sxy * inv - ux * uy);
        const float C1 = 1e-4f, C2 = 9e-4f;
        S = ((2.0f * ux * uy + C1) * (2.0f * vxy + C2)) /
            ((ux * ux + uy * uy + C1) * (vx + vy + C2));
    }
    float dmse = sxt[threadIdx.y][threadIdx.x] - syt[threadIdx.y][threadIdx.x];
    float msq = dmse * dmse;

    float totS = block_reduce_sum256(S, sh, tid);
    if (tid == 0) atomicAdd(&g_acc[1], (double)totS);
    __syncthreads();
    float totM = block_reduce_sum256(msq, sh, tid);
    if (tid == 0) atomicAdd(&g_acc[0], (double)totM);
}

// ---------------- conv1: both images, 1 -> 64 ch, relu, 32B records --------
__global__ void conv1_kernel(const float* __restrict__ sr, const float* __restrict__ hr,
                             const float* __restrict__ w,
                             const float* __restrict__ bias, unsigned* __restrict__ out) {
    __shared__ float sw[576];
    __shared__ float sb[64];
    int tid = threadIdx.x;
    for (int i = tid; i < 576; i += 256) sw[i] = w[i];
    if (tid < 64) sb[tid] = bias[tid];
    __syncthreads();
    int g = blockIdx.x * 256 + tid;          // 16*256*64 threads
    int x4 = (g & 63) * 4;
    int y  = (g >> 6) & 255;
    int b  = g >> 14;                        // 0..15
    const float* ib = (b < 8) ? (sr + (size_t)b * 65536)
                              : (hr + (size_t)(b - 8) * 65536);
    float inp[3][6];
    #pragma unroll
    for (int dy = 0; dy < 3; dy++) {
        int gy = y - 1 + dy;
        #pragma unroll
        for (int c = 0; c < 6; c++) {
            int gx = x4 - 1 + c;
            inp[dy][c] = ((unsigned)gy < 256u && (unsigned)gx < 256u) ? ib[gy * 256 + gx] : 0.0f;
        }
    }
    for (int blk = 0; blk < 4; blk++) {
        unsigned rec[4][8];
        for (int c = 0; c < 8; c++) {
            int coL = 16 * blk + c, coH = coL + 8;
            float aL[4], aH[4];
            #pragma unroll
            for (int p = 0; p < 4; p++) { aL[p] = sb[coL]; aH[p] = sb[coH]; }
            #pragma unroll
            for (int k = 0; k < 9; k++) {
                int ky = k / 3, kx = k - ky * 3;
                float wl = sw[coL * 9 + k], wh = sw[coH * 9 + k];
                #pragma unroll
                for (int p = 0; p < 4; p++) {
                    aL[p] = fmaf(inp[ky][p + kx], wl, aL[p]);
                    aH[p] = fmaf(inp[ky][p + kx], wh, aH[p]);
                }
            }
            int s = slot_of(c);
            #pragma unroll
            for (int p = 0; p < 4; p++)
                rec[p][s] = pack_h2(fmaxf(aL[p], 0.0f), fmaxf(aH[p], 0.0f));
        }
        #pragma unroll
        for (int p = 0; p < 4; p++) {
            size_t base = (((size_t)(b * 4 + blk)) * 65536 + (size_t)y * 256 + x4 + p) * 8;
            *(uint4*)(out + base)     = make_uint4(rec[p][0], rec[p][1], rec[p][2], rec[p][3]);
            *(uint4*)(out + base + 4) = make_uint4(rec[p][4], rec[p][5], rec[p][6], rec[p][7]);
        }
    }
}

// ---------------- weight pre-pack: fp16 m16n8k16 A-fragments ----------------
__global__ void pack_w_kernel(const float* __restrict__ w, unsigned* __restrict__ dst,
                              int Cin, int Cout) {
    int steps = Cin >> 4;
    int total = (Cout / 64) * steps * 4608;
    for (int idx = blockIdx.x * blockDim.x + threadIdx.x; idx < total;
         idx += gridDim.x * blockDim.x) {
        int reg = idx & 3;
        int k4  = (idx >> 2) & 3;
        int q   = (idx >> 4) & 7;
        int f   = (idx >> 7) & 1;
        int mw  = (idx >> 8) & 1;
        int tap = (idx >> 9) % 9;
        int rest = idx / 4608;
        int step = rest % steps;
        int cb   = rest / steps;
        int co = cb * 64 + mw * 32 + f * 16 + q + (reg & 1) * 8;
        int c  = k4 + (reg >> 1) * 4;
        int ci_lo = step * 16 + c;
        float lo = w[((size_t)co * Cin + ci_lo) * 9 + tap];
        float hi = w[((size_t)co * Cin + ci_lo + 8) * 9 + tap];
        dst[idx] = pack_h2(lo, hi);
    }
}

// ---------------- tensor-core 3x3 SAME conv (fp16 m16n8k16) ----------------
// R12-proven: 256 thr = 8 warps (2M x 4N), 128x2 strips, 64 co/CTA, K=16/step,
// 3-stage cp.async ring, one __syncthreads per step.
// mode 0: store ; 1: diff-reduce vs ref ; 2: fused 2x2 maxpool out (W=256).
template<int W>
__global__ __launch_bounds__(256, 2) void conv_mma(
    const unsigned* __restrict__ in, const unsigned* __restrict__ wpack,
    const float* __restrict__ bias,
    unsigned* __restrict__ out, const unsigned* __restrict__ ref,
    int Cin, int Cout, int mode)
{
    constexpr int H = W;
    constexpr int HW = W * W;
    constexpr int SCOLS = 130;
    constexpr int NPIX  = 4 * SCOLS;         // 520
    constexpr int SIN_U = NPIX * 8;          // 4160
    constexpr int SW_U  = 9 * 512;           // 4608
    constexpr int STRIPS = W >> 7;

    extern __shared__ unsigned smem_u[];
    unsigned* s_in = smem_u;                 // 3 buffers
    unsigned* s_w  = smem_u + 3 * SIN_U;     // 3 buffers
    __shared__ float s_red[32];

    int tid = threadIdx.x;
    int warp = tid >> 5;
    int lane = tid & 31;
    int q  = lane >> 2;
    int k4 = lane & 3;
    int mw = warp & 1;
    int nw = warp >> 1;
    int mwoff = mw * 32;
    int nwoff = nw * 64;

    int strip = blockIdx.x % STRIPS;
    int ypair = blockIdx.x / STRIPS;
    int y0 = ypair * 2;
    int c0 = strip << 7;
    int cb  = blockIdx.y;
    int co0 = cb * 64;
    int b   = blockIdx.z;
    int steps = Cin >> 4;

    unsigned s_in_u = (unsigned)__cvta_generic_to_shared(s_in);
    unsigned s_w_u  = (unsigned)__cvta_generic_to_shared(s_w);

    int awb0 = ((mw * 2 + 0) * 8 + q) * 16 + k4 * 4;
    int awb1 = awb0 + 128;

    int bb[8];
    #pragma unroll
    for (int nf = 0; nf < 8; nf++) {
        int base = nwoff + nf * 8;
        int ry   = base >> 7;
        int col  = base & 127;
        bb[nf] = ((ry * SCOLS + col) + q) * 8 + 2 * k4;
    }

    float acc[2][8][4];
    #pragma unroll
    for (int f = 0; f < 2; f++)
        #pragma unroll
        for (int nf = 0; nf < 8; nf++)
            #pragma unroll
            for (int e = 0; e < 4; e++) acc[f][nf][e] = 0.0f;

    const unsigned* inb = in + (size_t)b * (Cin >> 4) * HW * 8;
    const unsigned* wblk = wpack + (size_t)cb * steps * 4608;

    auto stage = [&](int step, int buf) {
        const unsigned* pbase = inb + (size_t)step * HW * 8;
        unsigned ibase = s_in_u + buf * SIN_U * 4;
        #pragma unroll 4
        for (int i = tid; i < NPIX * 2; i += 256) {
            int p = i >> 1;
            int half = i & 1;
            int r = p / SCOLS, cc = p - r * SCOLS;
            int gy = y0 - 1 + r;
            int gx = c0 + cc - 1;
            bool ok = ((unsigned)gy < (unsigned)H) && ((unsigned)gx < (unsigned)W);
            const unsigned* src = pbase + (size_t)(ok ? (gy * W + gx) : 0) * 8 + half * 4;
            cp_async16z(ibase + (unsigned)(p * 8 + half * 4) * 4, src, ok);
        }
        unsigned wbase = s_w_u + buf * SW_U * 4;
        const unsigned* wsrc = wblk + (size_t)step * 4608;
        #pragma unroll
        for (int i = tid; i < 1152; i += 256)
            cp_async16(wbase + (unsigned)i * 16, wsrc + i * 4);
    };

    stage(0, 0);
    cp_commit();
    if (steps > 1) { stage(1, 1); cp_commit(); }

    int buf = 0;
    for (int s = 0; s < steps; s++) {
        if (s + 1 < steps) { cp_wait<1>(); } else { cp_wait<0>(); }
        __syncthreads();
        if (s + 2 < steps) {
            int nbuf = buf + 2; if (nbuf >= 3) nbuf -= 3;
            stage(s + 2, nbuf);
            cp_commit();
        }

        const unsigned* bin = s_in + buf * SIN_U;
        const unsigned* bw  = s_w  + buf * SW_U;

        #pragma unroll
        for (int tap = 0; tap < 9; tap++) {
            const int ky = tap / 3, kx = tap - ky * 3;
            const int toff = (ky * SCOLS + kx) * 8;
            uint4 af0 = *(const uint4*)(bw + tap * 512 + awb0);
            uint4 af1 = *(const uint4*)(bw + tap * 512 + awb1);
            #pragma unroll
            for (int nf = 0; nf < 8; nf++) {
                uint2 bv = *(const uint2*)(bin + bb[nf] + toff);
                mma_f16(acc[0][nf], af0, bv);
                mma_f16(acc[1][nf], af1, bv);
            }
        }
        buf++; if (buf >= 3) buf = 0;
    }

    // ---- epilogue ----
    int sl = slot_of(q);
    if (mode == 0) {
        #pragma unroll
        for (int f = 0; f < 2; f++) {
            int coL = co0 + mwoff + f * 16 + q;
            float bv0 = __ldg(&bias[coL]);
            float bv8 = __ldg(&bias[coL + 8]);
            int plane = (co0 + mwoff + f * 16) >> 4;
            unsigned* pl = out + ((size_t)b * (Cout >> 4) + plane) * HW * 8;
            #pragma unroll
            for (int nf = 0; nf < 8; nf++) {
                int n = nwoff + nf * 8 + 2 * k4;
                int idx = (y0 + (n >> 7)) * W + c0 + (n & 127);
                pl[(size_t)idx * 8 + sl] =
                    pack_h2(fmaxf(acc[f][nf][0] + bv0, 0.0f),
                            fmaxf(acc[f][nf][2] + bv8, 0.0f));
                pl[(size_t)(idx + 1) * 8 + sl] =
                    pack_h2(fmaxf(acc[f][nf][1] + bv0, 0.0f),
                            fmaxf(acc[f][nf][3] + bv8, 0.0f));
            }
        }
    } else if (mode == 1) {
        float lsum = 0.0f;
        #pragma unroll
        for (int f = 0; f < 2; f++) {
            int coL = co0 + mwoff + f * 16 + q;
            float bv0 = __ldg(&bias[coL]);
            float bv8 = __ldg(&bias[coL + 8]);
            int plane = (co0 + mwoff + f * 16) >> 4;
            const unsigned* pl = ref + ((size_t)b * (Cout >> 4) + plane) * HW * 8;
            #pragma unroll
            for (int nf = 0; nf < 8; nf++) {
                int n = nwoff + nf * 8 + 2 * k4;
                int idx = (y0 + (n >> 7)) * W + c0 + (n & 127);
                float2 r0 = unpack_h2(pl[(size_t)idx * 8 + sl]);
                float2 r1 = unpack_h2(pl[(size_t)(idx + 1) * 8 + sl]);
                float d0 = h16r(fmaxf(acc[f][nf][0] + bv0, 0.0f)) - r0.x;
                float d1 = h16r(fmaxf(acc[f][nf][2] + bv8, 0.0f)) - r0.y;
                float d2 = h16r(fmaxf(acc[f][nf][1] + bv0, 0.0f)) - r1.x;
                float d3 = h16r(fmaxf(acc[f][nf][3] + bv8, 0.0f)) - r1.y;
                lsum = fmaf(d0, d0, lsum);
                lsum = fmaf(d1, d1, lsum);
                lsum = fmaf(d2, d2, lsum);
                lsum = fmaf(d3, d3, lsum);
            }
        }
        float tot = block_reduce_sum256(lsum, s_red, tid);
        if (tid == 0) atomicAdd(&g_acc[2], (double)tot);
    } else {
        // mode 2: fused 2x2 maxpool (W=256). spool[(row*128+x)*32 + lp]
        __syncthreads();
        unsigned* spool = s_in;
        #pragma unroll
        for (int f = 0; f < 2; f++) {
            int coL = co0 + mwoff + f * 16 + q;
            float bv0 = __ldg(&bias[coL]);
            float bv8 = __ldg(&bias[coL + 8]);
            int lp = ((mwoff + f * 16) >> 4) * 8 + q;
            #pragma unroll
            for (int nf = 0; nf < 8; nf++) {
                int n = nwoff + nf * 8 + 2 * k4;
                int row = n >> 7, x = n & 127;
                spool[(row * 128 + x) * 32 + lp] =
                    pack_h2(fmaxf(acc[f][nf][0] + bv0, 0.0f),
                            fmaxf(acc[f][nf][2] + bv8, 0.0f));
                spool[(row * 128 + x + 1) * 32 + lp] =
                    pack_h2(fmaxf(acc[f][nf][1] + bv0, 0.0f),
                            fmaxf(acc[f][nf][3] + bv8, 0.0f));
            }
        }
        __syncthreads();
        int ypix = ypair * 128 + (c0 >> 1);
        for (int i = tid; i < 2048; i += 256) {
            int lp = i >> 6;
            int X  = i & 63;
            unsigned m = hm2(hm2(spool[(2 * X) * 32 + lp],
                                 spool[(2 * X + 1) * 32 + lp]),
                             hm2(spool[(128 + 2 * X) * 32 + lp],
                                 spool[(129 + 2 * X) * 32 + lp]));
            int pl_loc = lp >> 3, c = lp & 7;
            out[(((size_t)b * 8 + cb * 4 + pl_loc) * 16384
                 + (size_t)(ypix + X)) * 8 + slot_of(c)] = m;
        }
    }
}

// ---------------- finalize ----------------
__global__ void finalize_kernel(float* out, int out_size) {
    double mse    = g_acc[0] / 524288.0;
    double ssim_l = 1.0 - g_acc[1] / 500000.0;
    double perc   = g_acc[2] / 33554432.0;
    double total  = mse + 0.5 * ssim_l + 0.1 * perc;
    float vals[4] = {(float)total, (float)mse, (float)ssim_l, (float)perc};
    for (int i = 0; i < 4 && i < out_size; i++) out[i] = vals[i];
}

// ---------------- launcher ----------------
extern "C" void kernel_launch(void* const* d_in, const int* in_sizes, int n_in,
                              void* d_out, int out_size) {
    (void)in_sizes; (void)n_in;
    const float* sr = (const float*)d_in[0];
    const float* hr = (const float*)d_in[1];
    const float* w1 = (const float*)d_in[2];
    const float* b1 = (const float*)d_in[3];
    const float* w2 = (const float*)d_in[4];
    const float* b2 = (const float*)d_in[5];
    const float* w3 = (const float*)d_in[6];
    const float* b3 = (const float*)d_in[7];
    const float* w4 = (const float*)d_in[8];
    const float* b4 = (const float*)d_in[9];
    float* out = (float*)d_out;

    unsigned *A, *P, *C, *D, *WP;
    cudaGetSymbolAddress((void**)&A, g_bufA);
    cudaGetSymbolAddress((void**)&P, g_bufP);
    cudaGetSymbolAddress((void**)&C, g_bufC);
    cudaGetSymbolAddress((void**)&D, g_bufD);
    cudaGetSymbolAddress((void**)&WP, g_wpk);
    unsigned* WP2 = WP;             // 36864 u32
    unsigned* WP3 = WP + 36864;     // 147456 u32
    unsigned* WP4 = WP + 184320;    // 294912 u32

    const int smem = (3 * 4160 + 3 * 4608) * 4;   // 105216 B (3-stage ring)
    cudaFuncSetAttribute(conv_mma<256>, cudaFuncAttributeMaxDynamicSharedMemorySize, smem);
    cudaFuncSetAttribute(conv_mma<128>, cudaFuncAttributeMaxDynamicSharedMemorySize, smem);

    zero_acc_kernel<<<1, 1>>>();
    pack_w_kernel<<<144, 256>>>(w2, WP2, 64, 128);
    pack_w_kernel<<<576, 256>>>(w3, WP3, 128, 256);
    pack_w_kernel<<<1152, 256>>>(w4, WP4, 256, 256);

    // conv1 for BOTH images (z folded into blockIdx.x: 16*256*64 threads)
    conv1_kernel<<<1024, 256>>>(sr, hr, w1, b1, A);
    // conv2 + fused pool for both (z = 16)
    conv_mma<256><<<dim3(256, 2, 16), 256, smem>>>(A, WP2, b2, P, nullptr, 64, 128, 2);
    // conv3 for both (z = 16)
    conv_mma<128><<<dim3(64, 4, 16), 256, smem>>>(P, WP3, b3, C, nullptr, 128, 256, 0);
    // conv4 sr: store D (z = 8, batches 0..7 of C)
    conv_mma<128><<<dim3(64, 4, 8), 256, smem>>>(C, WP4, b4, D, nullptr, 256, 256, 0);
    // SSIM + fused MSE (overlaps tail of conv pipeline region in-order anyway)
    ssim_kernel<<<dim3(16, 16, 8), dim3(16, 16)>>>(sr, hr);
    // conv4 hr: diff vs D (batches 8..15 of C)
    conv_mma<128><<<dim3(64, 4, 8), 256, smem>>>(C + (size_t)8 * 16 * 16384 * 8,
                                                 WP4, b4, nullptr, D, 256, 256, 1);

    finalize_kernel<<<1, 1>>>(out, out_size);
}

// round 16
// speedup vs baseline: 1.0584x; 1.0039x over previous
#include <cuda_runtime.h>
#include <cuda_fp16.h>
#include <cstdint>

// ---------------- scratch (device globals; no allocation allowed) ----------
// Activations: [bb][plane=16ch][HW px][8 u32 record], record slot-permuted
// fp16x2 pairs: slot(c) = (c&3)*2+(c>>2) holds channels (c, c+8).
// bb = 0..7 sr images, 8..15 hr images.
__device__ unsigned g_bufA[33554432];  // conv1 out (16,4pl,65536,8)
__device__ unsigned g_bufP[16777216];  // pooled    (16,8pl,16384,8)
__device__ unsigned g_bufC[33554432];  // conv3 out (16,16pl,16384,8)
__device__ unsigned g_bufD[16777216];  // conv4 out sr pass (8,16pl,16384,8)
__device__ unsigned g_wpk[524288];     // packed fp16 A-fragment weights
__device__ double g_acc[3];            // 0: mse, 1: ssim, 2: perceptual

// ---------------- helpers ----------------
__device__ __forceinline__ float block_reduce_sum256(float v, float* sh, int tid) {
    #pragma unroll
    for (int o = 16; o > 0; o >>= 1) v += __shfl_down_sync(0xffffffffu, v, o);
    if ((tid & 31) == 0) sh[tid >> 5] = v;
    __syncthreads();
    if (tid < 32) {
        v = (tid < 8) ? sh[tid] : 0.0f;
        #pragma unroll
        for (int o = 4; o > 0; o >>= 1) v += __shfl_down_sync(0xffffffffu, v, o);
    }
    return v;
}
__device__ __forceinline__ unsigned pack_h2(float lo, float hi) {
    __half2 h = __floats2half2_rn(lo, hi);
    return *(unsigned*)&h;
}
__device__ __forceinline__ float2 unpack_h2(unsigned u) {
    __half2 h = *(__half2*)&u;
    return __half22float2(h);
}
__device__ __forceinline__ float h16r(float x) {
    return __half2float(__float2half_rn(x));
}
__device__ __forceinline__ unsigned hm2(unsigned a, unsigned b) {
    __half2 r = __hmax2(*(__half2*)&a, *(__half2*)&b);
    return *(unsigned*)&r;
}
__device__ __forceinline__ void mma_f16(float* c, const uint4 a, const uint2 b) {
    asm volatile(
        "mma.sync.aligned.m16n8k16.row.col.f32.f16.f16.f32 "
        "{%0,%1,%2,%3}, {%4,%5,%6,%7}, {%8,%9}, {%0,%1,%2,%3};"
        : "+f"(c[0]), "+f"(c[1]), "+f"(c[2]), "+f"(c[3])
        : "r"(a.x), "r"(a.y), "r"(a.z), "r"(a.w), "r"(b.x), "r"(b.y));
}
__device__ __forceinline__ void cp_async16(unsigned dst, const void* src) {
    asm volatile("cp.async.cg.shared.global [%0], [%1], 16;" :: "r"(dst), "l"(src));
}
__device__ __forceinline__ void cp_async16z(unsigned dst, const void* src, bool ok) {
    int sz = ok ? 16 : 0;
    asm volatile("cp.async.cg.shared.global [%0], [%1], 16, %2;"
                 :: "r"(dst), "l"(src), "r"(sz));
}
__device__ __forceinline__ void cp_commit() { asm volatile("cp.async.commit_group;"); }
template<int N> __device__ __forceinline__ void cp_wait() {
    asm volatile("cp.async.wait_group %0;" :: "n"(N));
}
__device__ __forceinline__ int slot_of(int c) { return ((c & 3) << 1) + (c >> 2); }

// ---------------- SSIM + fused MSE ----------------
__global__ void ssim_kernel(const float* __restrict__ x, const float* __restrict__ y) {
    __shared__ float sxt[22][23];
    __shared__ float syt[22][23];
    __shared__ float sh[32];
    int b = blockIdx.z;
    int gx0 = blockIdx.x * 16, gy0 = blockIdx.y * 16;
    const float* xb = x + (size_t)b * 65536;
    const float* yb = y + (size_t)b * 65536;
    int tid = threadIdx.y * 16 + threadIdx.x;
    for (int i = tid; i < 22 * 22; i += 256) {
        int rr = i / 22, cc = i - rr * 22;
        int gy = gy0 + rr, gx = gx0 + cc;
        float vx = 0.0f, vy = 0.0f;
        if (gy < 256 && gx < 256) { vx = xb[gy * 256 + gx]; vy = yb[gy * 256 + gx]; }
        sxt[rr][cc] = vx; syt[rr][cc] = vy;
    }
    __syncthreads();
    int i = gy0 + threadIdx.y, j = gx0 + threadIdx.x;
    float S = 0.0f;
    if (i < 250 && j < 250) {
        float sx = 0, sy = 0, sxx = 0, syy = 0, sxy = 0;
        #pragma unroll
        for (int dy = 0; dy < 7; dy++)
            #pragma unroll
            for (int dx = 0; dx < 7; dx++) {
                float a = sxt[threadIdx.y + dy][threadIdx.x + dx];
                float c = syt[threadIdx.y + dy][threadIdx.x + dx];
                sx += a; sy += c;
                sxx = fmaf(a, a, sxx); syy = fmaf(c, c, syy); sxy = fmaf(a, c, sxy);
            }
        const float inv = 1.0f / 49.0f, cn = 49.0f / 48.0f;
        float ux = sx * inv, uy = sy * inv;
        float vx  = cn * (sxx * inv - ux * ux);
        float vy  = cn * (syy * inv - uy * uy);
        float vxy = cn * (sxy * inv - ux * uy);
        const float C1 = 1e-4f, C2 = 9e-4f;
        S = ((2.0f * ux * uy + C1) * (2.0f * vxy + C2)) /
            ((ux * ux + uy * uy + C1) * (vx + vy + C2));
    }
    float dmse = sxt[threadIdx.y][threadIdx.x] - syt[threadIdx.y][threadIdx.x];
    float msq = dmse * dmse;

    float totS = block_reduce_sum256(S, sh, tid);
    if (tid == 0) atomicAdd(&g_acc[1], (double)totS);
    __syncthreads();
    float totM = block_reduce_sum256(msq, sh, tid);
    if (tid == 0) atomicAdd(&g_acc[0], (double)totM);
}

// ---------------- conv1: both images, 1 -> 64 ch, relu, 32B records --------
__global__ void conv1_kernel(const float* __restrict__ sr, const float* __restrict__ hr,
                             const float* __restrict__ w,
                             const float* __restrict__ bias, unsigned* __restrict__ out) {
    __shared__ float sw[576];
    __shared__ float sb[64];
    int tid = threadIdx.x;
    for (int i = tid; i < 576; i += 256) sw[i] = w[i];
    if (tid < 64) sb[tid] = bias[tid];
    __syncthreads();
    int g = blockIdx.x * 256 + tid;          // 16*256*64 threads
    int x4 = (g & 63) * 4;
    int y  = (g >> 6) & 255;
    int b  = g >> 14;                        // 0..15
    const float* ib = (b < 8) ? (sr + (size_t)b * 65536)
                              : (hr + (size_t)(b - 8) * 65536);
    // vectorized halo load: rows y-1..y+1, cols x4-1..x4+4
    float inp[3][6];
    #pragma unroll
    for (int dy = 0; dy < 3; dy++) {
        int gy = y - 1 + dy;
        if ((unsigned)gy < 256u) {
            const float* row = ib + gy * 256;
            float4 v = *(const float4*)(row + x4);          // x4 aligned, in-bounds
            inp[dy][1] = v.x; inp[dy][2] = v.y; inp[dy][3] = v.z; inp[dy][4] = v.w;
            inp[dy][0] = (x4 > 0)        ? row[x4 - 1] : 0.0f;
            inp[dy][5] = (x4 + 4 < 256)  ? row[x4 + 4] : 0.0f;
        } else {
            #pragma unroll
            for (int c = 0; c < 6; c++) inp[dy][c] = 0.0f;
        }
    }
    for (int blk = 0; blk < 4; blk++) {
        unsigned rec[4][8];
        for (int c = 0; c < 8; c++) {
            int coL = 16 * blk + c, coH = coL + 8;
            float aL[4], aH[4];
            #pragma unroll
            for (int p = 0; p < 4; p++) { aL[p] = sb[coL]; aH[p] = sb[coH]; }
            #pragma unroll
            for (int k = 0; k < 9; k++) {
                int ky = k / 3, kx = k - ky * 3;
                float wl = sw[coL * 9 + k], wh = sw[coH * 9 + k];
                #pragma unroll
                for (int p = 0; p < 4; p++) {
                    aL[p] = fmaf(inp[ky][p + kx], wl, aL[p]);
                    aH[p] = fmaf(inp[ky][p + kx], wh, aH[p]);
                }
            }
            int s = slot_of(c);
            #pragma unroll
            for (int p = 0; p < 4; p++)
                rec[p][s] = pack_h2(fmaxf(aL[p], 0.0f), fmaxf(aH[p], 0.0f));
        }
        #pragma unroll
        for (int p = 0; p < 4; p++) {
            size_t base = (((size_t)(b * 4 + blk)) * 65536 + (size_t)y * 256 + x4 + p) * 8;
            *(uint4*)(out + base)     = make_uint4(rec[p][0], rec[p][1], rec[p][2], rec[p][3]);
            *(uint4*)(out + base + 4) = make_uint4(rec[p][4], rec[p][5], rec[p][6], rec[p][7]);
        }
    }
}

// ---------------- unified weight pre-pack (conv2|conv3|conv4) + acc zero ----
// Packs all three weight sets in one launch. Layout per set unchanged:
// [cb][step][tap(9)][512 u32]; inner ((mw*2+f)*8+q)*16 + k4*4 + reg.
__global__ void pack_all_kernel(const float* __restrict__ w2,
                                const float* __restrict__ w3,
                                const float* __restrict__ w4,
                                unsigned* __restrict__ dst) {
    if (blockIdx.x == 0 && threadIdx.x == 0) {
        g_acc[0] = 0.0; g_acc[1] = 0.0; g_acc[2] = 0.0;
    }
    // set sizes (u32): conv2 36864 @0 ; conv3 147456 @36864 ; conv4 294912 @184320
    int total = 36864 + 147456 + 294912;    // 479232
    for (int gidx = blockIdx.x * blockDim.x + threadIdx.x; gidx < total;
         gidx += gridDim.x * blockDim.x) {
        const float* w;
        int idx, Cin;
        if (gidx < 36864)        { w = w2; idx = gidx;          Cin = 64;  }
        else if (gidx < 184320)  { w = w3; idx = gidx - 36864;  Cin = 128; }
        else                     { w = w4; idx = gidx - 184320; Cin = 256; }
        int steps = Cin >> 4;
        int reg = idx & 3;
        int k4  = (idx >> 2) & 3;
        int q   = (idx >> 4) & 7;
        int f   = (idx >> 7) & 1;
        int mw  = (idx >> 8) & 1;
        int tap = (idx >> 9) % 9;
        int rest = idx / 4608;
        int step = rest % steps;
        int cb   = rest / steps;
        int co = cb * 64 + mw * 32 + f * 16 + q + (reg & 1) * 8;
        int c  = k4 + (reg >> 1) * 4;
        int ci_lo = step * 16 + c;
        float lo = w[((size_t)co * Cin + ci_lo) * 9 + tap];
        float hi = w[((size_t)co * Cin + ci_lo + 8) * 9 + tap];
        dst[gidx] = pack_h2(lo, hi);
    }
}

// ---------------- tensor-core 3x3 SAME conv (fp16 m16n8k16) ----------------
// R12-proven: 256 thr = 8 warps (2M x 4N), 128x2 strips, 64 co/CTA, K=16/step,
// 3-stage cp.async ring, one __syncthreads per step.
// mode 0: store ; 1: diff-reduce vs ref ; 2: fused 2x2 maxpool out (W=256).
template<int W>
__global__ __launch_bounds__(256, 2) void conv_mma(
    const unsigned* __restrict__ in, const unsigned* __restrict__ wpack,
    const float* __restrict__ bias,
    unsigned* __restrict__ out, const unsigned* __restrict__ ref,
    int Cin, int Cout, int mode)
{
    constexpr int H = W;
    constexpr int HW = W * W;
    constexpr int SCOLS = 130;
    constexpr int NPIX  = 4 * SCOLS;         // 520
    constexpr int SIN_U = NPIX * 8;          // 4160
    constexpr int SW_U  = 9 * 512;           // 4608
    constexpr int STRIPS = W >> 7;

    extern __shared__ unsigned smem_u[];
    unsigned* s_in = smem_u;                 // 3 buffers
    unsigned* s_w  = smem_u + 3 * SIN_U;     // 3 buffers
    __shared__ float s_red[32];

    int tid = threadIdx.x;
    int warp = tid >> 5;
    int lane = tid & 31;
    int q  = lane >> 2;
    int k4 = lane & 3;
    int mw = warp & 1;
    int nw = warp >> 1;
    int mwoff = mw * 32;
    int nwoff = nw * 64;

    int strip = blockIdx.x % STRIPS;
    int ypair = blockIdx.x / STRIPS;
    int y0 = ypair * 2;
    int c0 = strip << 7;
    int cb  = blockIdx.y;
    int co0 = cb * 64;
    int b   = blockIdx.z;
    int steps = Cin >> 4;

    unsigned s_in_u = (unsigned)__cvta_generic_to_shared(s_in);
    unsigned s_w_u  = (unsigned)__cvta_generic_to_shared(s_w);

    int awb0 = ((mw * 2 + 0) * 8 + q) * 16 + k4 * 4;
    int awb1 = awb0 + 128;

    int bb[8];
    #pragma unroll
    for (int nf = 0; nf < 8; nf++) {
        int base = nwoff + nf * 8;
        int ry   = base >> 7;
        int col  = base & 127;
        bb[nf] = ((ry * SCOLS + col) + q) * 8 + 2 * k4;
    }

    float acc[2][8][4];
    #pragma unroll
    for (int f = 0; f < 2; f++)
        #pragma unroll
        for (int nf = 0; nf < 8; nf++)
            #pragma unroll
            for (int e = 0; e < 4; e++) acc[f][nf][e] = 0.0f;

    const unsigned* inb = in + (size_t)b * (Cin >> 4) * HW * 8;
    const unsigned* wblk = wpack + (size_t)cb * steps * 4608;

    auto stage = [&](int step, int buf) {
        const unsigned* pbase = inb + (size_t)step * HW * 8;
        unsigned ibase = s_in_u + buf * SIN_U * 4;
        #pragma unroll 4
        for (int i = tid; i < NPIX * 2; i += 256) {
            int p = i >> 1;
            int half = i & 1;
            int r = p / SCOLS, cc = p - r * SCOLS;
            int gy = y0 - 1 + r;
            int gx = c0 + cc - 1;
            bool ok = ((unsigned)gy < (unsigned)H) && ((unsigned)gx < (unsigned)W);
            const unsigned* src = pbase + (size_t)(ok ? (gy * W + gx) : 0) * 8 + half * 4;
            cp_async16z(ibase + (unsigned)(p * 8 + half * 4) * 4, src, ok);
        }
        unsigned wbase = s_w_u + buf * SW_U * 4;
        const unsigned* wsrc = wblk + (size_t)step * 4608;
        #pragma unroll
        for (int i = tid; i < 1152; i += 256)
            cp_async16(wbase + (unsigned)i * 16, wsrc + i * 4);
    };

    stage(0, 0);
    cp_commit();
    if (steps > 1) { stage(1, 1); cp_commit(); }

    int buf = 0;
    for (int s = 0; s < steps; s++) {
        if (s + 1 < steps) { cp_wait<1>(); } else { cp_wait<0>(); }
        __syncthreads();
        if (s + 2 < steps) {
            int nbuf = buf + 2; if (nbuf >= 3) nbuf -= 3;
            stage(s + 2, nbuf);
            cp_commit();
        }

        const unsigned* bin = s_in + buf * SIN_U;
        const unsigned* bw  = s_w  + buf * SW_U;

        #pragma unroll
        for (int tap = 0; tap < 9; tap++) {
            const int ky = tap / 3, kx = tap - ky * 3;
            const int toff = (ky * SCOLS + kx) * 8;
            uint4 af0 = *(const uint4*)(bw + tap * 512 + awb0);
            uint4 af1 = *(const uint4*)(bw + tap * 512 + awb1);
            #pragma unroll
            for (int nf = 0; nf < 8; nf++) {
                uint2 bv = *(const uint2*)(bin + bb[nf] + toff);
                mma_f16(acc[0][nf], af0, bv);
                mma_f16(acc[1][nf], af1, bv);
            }
        }
        buf++; if (buf >= 3) buf = 0;
    }

    // ---- epilogue ----
    int sl = slot_of(q);
    if (mode == 0) {
        #pragma unroll
        for (int f = 0; f < 2; f++) {
            int coL = co0 + mwoff + f * 16 + q;
            float bv0 = __ldg(&bias[coL]);
            float bv8 = __ldg(&bias[coL + 8]);
            int plane = (co0 + mwoff + f * 16) >> 4;
            unsigned* pl = out + ((size_t)b * (Cout >> 4) + plane) * HW * 8;
            #pragma unroll
            for (int nf = 0; nf < 8; nf++) {
                int n = nwoff + nf * 8 + 2 * k4;
                int idx = (y0 + (n >> 7)) * W + c0 + (n & 127);
                pl[(size_t)idx * 8 + sl] =
                    pack_h2(fmaxf(acc[f][nf][0] + bv0, 0.0f),
                            fmaxf(acc[f][nf][2] + bv8, 0.0f));
                pl[(size_t)(idx + 1) * 8 + sl] =
                    pack_h2(fmaxf(acc[f][nf][1] + bv0, 0.0f),
                            fmaxf(acc[f][nf][3] + bv8, 0.0f));
            }
        }
    } else if (mode == 1) {
        float lsum = 0.0f;
        #pragma unroll
        for (int f = 0; f < 2; f++) {
            int coL = co0 + mwoff + f * 16 + q;
            float bv0 = __ldg(&bias[coL]);
            float bv8 = __ldg(&bias[coL + 8]);
            int plane = (co0 + mwoff + f * 16) >> 4;
            const unsigned* pl = ref + ((size_t)b * (Cout >> 4) + plane) * HW * 8;
            #pragma unroll
            for (int nf = 0; nf < 8; nf++) {
                int n = nwoff + nf * 8 + 2 * k4;
                int idx = (y0 + (n >> 7)) * W + c0 + (n & 127);
                float2 r0 = unpack_h2(pl[(size_t)idx * 8 + sl]);
                float2 r1 = unpack_h2(pl[(size_t)(idx + 1) * 8 + sl]);
                float d0 = h16r(fmaxf(acc[f][nf][0] + bv0, 0.0f)) - r0.x;
                float d1 = h16r(fmaxf(acc[f][nf][2] + bv8, 0.0f)) - r0.y;
                float d2 = h16r(fmaxf(acc[f][nf][1] + bv0, 0.0f)) - r1.x;
                float d3 = h16r(fmaxf(acc[f][nf][3] + bv8, 0.0f)) - r1.y;
                lsum = fmaf(d0, d0, lsum);
                lsum = fmaf(d1, d1, lsum);
                lsum = fmaf(d2, d2, lsum);
                lsum = fmaf(d3, d3, lsum);
            }
        }
        float tot = block_reduce_sum256(lsum, s_red, tid);
        if (tid == 0) atomicAdd(&g_acc[2], (double)tot);
    } else {
        // mode 2: fused 2x2 maxpool (W=256). spool[(row*128+x)*32 + lp]
        __syncthreads();
        unsigned* spool = s_in;
        #pragma unroll
        for (int f = 0; f < 2; f++) {
            int coL = co0 + mwoff + f * 16 + q;
            float bv0 = __ldg(&bias[coL]);
            float bv8 = __ldg(&bias[coL + 8]);
            int lp = ((mwoff + f * 16) >> 4) * 8 + q;
            #pragma unroll
            for (int nf = 0; nf < 8; nf++) {
                int n = nwoff + nf * 8 + 2 * k4;
                int row = n >> 7, x = n & 127;
                spool[(row * 128 + x) * 32 + lp] =
                    pack_h2(fmaxf(acc[f][nf][0] + bv0, 0.0f),
                            fmaxf(acc[f][nf][2] + bv8, 0.0f));
                spool[(row * 128 + x + 1) * 32 + lp] =
                    pack_h2(fmaxf(acc[f][nf][1] + bv0, 0.0f),
                            fmaxf(acc[f][nf][3] + bv8, 0.0f));
            }
        }
        __syncthreads();
        int ypix = ypair * 128 + (c0 >> 1);
        for (int i = tid; i < 2048; i += 256) {
            int lp = i >> 6;
            int X  = i & 63;
            unsigned m = hm2(hm2(spool[(2 * X) * 32 + lp],
                                 spool[(2 * X + 1) * 32 + lp]),
                             hm2(spool[(128 + 2 * X) * 32 + lp],
                                 spool[(129 + 2 * X) * 32 + lp]));
            int pl_loc = lp >> 3, c = lp & 7;
            out[(((size_t)b * 8 + cb * 4 + pl_loc) * 16384
                 + (size_t)(ypix + X)) * 8 + slot_of(c)] = m;
        }
    }
}

// ---------------- finalize ----------------
__global__ void finalize_kernel(float* out, int out_size) {
    double mse    = g_acc[0] / 524288.0;
    double ssim_l = 1.0 - g_acc[1] / 500000.0;
    double perc   = g_acc[2] / 33554432.0;
    double total  = mse + 0.5 * ssim_l + 0.1 * perc;
    float vals[4] = {(float)total, (float)mse, (float)ssim_l, (float)perc};
    for (int i = 0; i < 4 && i < out_size; i++) out[i] = vals[i];
}

// ---------------- launcher ----------------
extern "C" void kernel_launch(void* const* d_in, const int* in_sizes, int n_in,
                              void* d_out, int out_size) {
    (void)in_sizes; (void)n_in;
    const float* sr = (const float*)d_in[0];
    const float* hr = (const float*)d_in[1];
    const float* w1 = (const float*)d_in[2];
    const float* b1 = (const float*)d_in[3];
    const float* w2 = (const float*)d_in[4];
    const float* b2 = (const float*)d_in[5];
    const float* w3 = (const float*)d_in[6];
    const float* b3 = (const float*)d_in[7];
    const float* w4 = (const float*)d_in[8];
    const float* b4 = (const float*)d_in[9];
    float* out = (float*)d_out;

    unsigned *A, *P, *C, *D, *WP;
    cudaGetSymbolAddress((void**)&A, g_bufA);
    cudaGetSymbolAddress((void**)&P, g_bufP);
    cudaGetSymbolAddress((void**)&C, g_bufC);
    cudaGetSymbolAddress((void**)&D, g_bufD);
    cudaGetSymbolAddress((void**)&WP, g_wpk);
    unsigned* WP2 = WP;             // 36864 u32
    unsigned* WP3 = WP + 36864;     // 147456 u32
    unsigned* WP4 = WP + 184320;    // 294912 u32

    const int smem = (3 * 4160 + 3 * 4608) * 4;   // 105216 B (3-stage ring)
    cudaFuncSetAttribute(conv_mma<256>, cudaFuncAttributeMaxDynamicSharedMemorySize, smem);
    cudaFuncSetAttribute(conv_mma<128>, cudaFuncAttributeMaxDynamicSharedMemorySize, smem);

    // one prologue launch: zero accumulators + pack all weights
    pack_all_kernel<<<1872, 256>>>(w2, w3, w4, WP);

    // conv1 for BOTH images (16*256*64 threads)
    conv1_kernel<<<1024, 256>>>(sr, hr, w1, b1, A);
    // conv2 + fused pool for both (z = 16)
    conv_mma<256><<<dim3(256, 2, 16), 256, smem>>>(A, WP2, b2, P, nullptr, 64, 128, 2);
    // conv3 for both (z = 16)
    conv_mma<128><<<dim3(64, 4, 16), 256, smem>>>(P, WP3, b3, C, nullptr, 128, 256, 0);
    // conv4 sr: store D (z = 8, batches 0..7 of C)
    conv_mma<128><<<dim3(64, 4, 8), 256, smem>>>(C, WP4, b4, D, nullptr, 256, 256, 0);
    // SSIM + fused MSE
    ssim_kernel<<<dim3(16, 16, 8), dim3(16, 16)>>>(sr, hr);
    // conv4 hr: diff vs D (batches 8..15 of C)
    conv_mma<128><<<dim3(64, 4, 8), 256, smem>>>(C + (size_t)8 * 16 * 16384 * 8,
                                                 WP4, b4, nullptr, D, 256, 256, 1);

    finalize_kernel<<<1, 1>>>(out, out_size);
}

// round 17
// speedup vs baseline: 1.2079x; 1.1412x over previous
#include <cuda_runtime.h>
#include <cuda_fp16.h>
#include <cstdint>

// ---------------- scratch (device globals; no allocation allowed) ----------
// Activations: [bb][plane=16ch][HW px][8 u32 record], record slot-permuted
// fp16x2 pairs: slot(c) = (c&3)*2+(c>>2) holds channels (c, c+8).
// bb = 0..7 sr images, 8..15 hr images.
__device__ unsigned g_bufA[33554432];  // conv1 out (16,4pl,65536,8)
__device__ unsigned g_bufP[16777216];  // pooled    (16,8pl,16384,8)
__device__ unsigned g_bufC[33554432];  // conv3 out (16,16pl,16384,8)
__device__ unsigned g_bufD[16777216];  // conv4 out sr pass (8,16pl,16384,8)
__device__ unsigned g_wpk[524288];     // packed fp16 A-fragment weights
__device__ double g_acc[3];            // 0: mse, 1: ssim, 2: perceptual

// ---------------- helpers ----------------
__device__ __forceinline__ float block_reduce_sum256(float v, float* sh, int tid) {
    #pragma unroll
    for (int o = 16; o > 0; o >>= 1) v += __shfl_down_sync(0xffffffffu, v, o);
    if ((tid & 31) == 0) sh[tid >> 5] = v;
    __syncthreads();
    if (tid < 32) {
        v = (tid < 8) ? sh[tid] : 0.0f;
        #pragma unroll
        for (int o = 4; o > 0; o >>= 1) v += __shfl_down_sync(0xffffffffu, v, o);
    }
    return v;
}
__device__ __forceinline__ unsigned pack_h2(float lo, float hi) {
    __half2 h = __floats2half2_rn(lo, hi);
    return *(unsigned*)&h;
}
__device__ __forceinline__ float2 unpack_h2(unsigned u) {
    __half2 h = *(__half2*)&u;
    return __half22float2(h);
}
__device__ __forceinline__ float h16r(float x) {
    return __half2float(__float2half_rn(x));
}
__device__ __forceinline__ void mma_f16(float* c, const uint4 a, const uint2 b) {
    asm volatile(
        "mma.sync.aligned.m16n8k16.row.col.f32.f16.f16.f32 "
        "{%0,%1,%2,%3}, {%4,%5,%6,%7}, {%8,%9}, {%0,%1,%2,%3};"
        : "+f"(c[0]), "+f"(c[1]), "+f"(c[2]), "+f"(c[3])
        : "r"(a.x), "r"(a.y), "r"(a.z), "r"(a.w), "r"(b.x), "r"(b.y));
}
__device__ __forceinline__ void cp_async16(unsigned dst, const void* src) {
    asm volatile("cp.async.cg.shared.global [%0], [%1], 16;" :: "r"(dst), "l"(src));
}
__device__ __forceinline__ void cp_async16z(unsigned dst, const void* src, bool ok) {
    int sz = ok ? 16 : 0;
    asm volatile("cp.async.cg.shared.global [%0], [%1], 16, %2;"
                 :: "r"(dst), "l"(src), "r"(sz));
}
__device__ __forceinline__ void cp_commit() { asm volatile("cp.async.commit_group;"); }
template<int N> __device__ __forceinline__ void cp_wait() {
    asm volatile("cp.async.wait_group %0;" :: "n"(N));
}
__device__ __forceinline__ int slot_of(int c) { return ((c & 3) << 1) + (c >> 2); }

// ---------------- SSIM + fused MSE ----------------
__global__ void ssim_kernel(const float* __restrict__ x, const float* __restrict__ y) {
    __shared__ float sxt[22][23];
    __shared__ float syt[22][23];
    __shared__ float sh[32];
    int b = blockIdx.z;
    int gx0 = blockIdx.x * 16, gy0 = blockIdx.y * 16;
    const float* xb = x + (size_t)b * 65536;
    const float* yb = y + (size_t)b * 65536;
    int tid = threadIdx.y * 16 + threadIdx.x;
    for (int i = tid; i < 22 * 22; i += 256) {
        int rr = i / 22, cc = i - rr * 22;
        int gy = gy0 + rr, gx = gx0 + cc;
        float vx = 0.0f, vy = 0.0f;
        if (gy < 256 && gx < 256) { vx = xb[gy * 256 + gx]; vy = yb[gy * 256 + gx]; }
        sxt[rr][cc] = vx; syt[rr][cc] = vy;
    }
    __syncthreads();
    int i = gy0 + threadIdx.y, j = gx0 + threadIdx.x;
    float S = 0.0f;
    if (i < 250 && j < 250) {
        float sx = 0, sy = 0, sxx = 0, syy = 0, sxy = 0;
        #pragma unroll
        for (int dy = 0; dy < 7; dy++)
            #pragma unroll
            for (int dx = 0; dx < 7; dx++) {
                float a = sxt[threadIdx.y + dy][threadIdx.x + dx];
                float c = syt[threadIdx.y + dy][threadIdx.x + dx];
                sx += a; sy += c;
                sxx = fmaf(a, a, sxx); syy = fmaf(c, c, syy); sxy = fmaf(a, c, sxy);
            }
        const float inv = 1.0f / 49.0f, cn = 49.0f / 48.0f;
        float ux = sx * inv, uy = sy * inv;
        float vx  = cn * (sxx * inv - ux * ux);
        float vy  = cn * (syy * inv - uy * uy);
        float vxy = cn * (sxy * inv - ux * uy);
        const float C1 = 1e-4f, C2 = 9e-4f;
        S = ((2.0f * ux * uy + C1) * (2.0f * vxy + C2)) /
            ((ux * ux + uy * uy + C1) * (vx + vy + C2));
    }
    float dmse = sxt[threadIdx.y][threadIdx.x] - syt[threadIdx.y][threadIdx.x];
    float msq = dmse * dmse;

    float totS = block_reduce_sum256(S, sh, tid);
    if (tid == 0) atomicAdd(&g_acc[1], (double)totS);
    __syncthreads();
    float totM = block_reduce_sum256(msq, sh, tid);
    if (tid == 0) atomicAdd(&g_acc[0], (double)totM);
}

// ---------------- conv1: both images, 1 -> 64 ch, relu, 32B records --------
__global__ void conv1_kernel(const float* __restrict__ sr, const float* __restrict__ hr,
                             const float* __restrict__ w,
                             const float* __restrict__ bias, unsigned* __restrict__ out) {
    __shared__ float sw[576];
    __shared__ float sb[64];
    int tid = threadIdx.x;
    for (int i = tid; i < 576; i += 256) sw[i] = w[i];
    if (tid < 64) sb[tid] = bias[tid];
    __syncthreads();
    int g = blockIdx.x * 256 + tid;          // 16*256*64 threads
    int x4 = (g & 63) * 4;
    int y  = (g >> 6) & 255;
    int b  = g >> 14;                        // 0..15
    const float* ib = (b < 8) ? (sr + (size_t)b * 65536)
                              : (hr + (size_t)(b - 8) * 65536);
    float inp[3][6];
    #pragma unroll
    for (int dy = 0; dy < 3; dy++) {
        int gy = y - 1 + dy;
        if ((unsigned)gy < 256u) {
            const float* row = ib + gy * 256;
            float4 v = *(const float4*)(row + x4);
            inp[dy][1] = v.x; inp[dy][2] = v.y; inp[dy][3] = v.z; inp[dy][4] = v.w;
            inp[dy][0] = (x4 > 0)       ? row[x4 - 1] : 0.0f;
            inp[dy][5] = (x4 + 4 < 256) ? row[x4 + 4] : 0.0f;
        } else {
            #pragma unroll
            for (int c = 0; c < 6; c++) inp[dy][c] = 0.0f;
        }
    }
    for (int blk = 0; blk < 4; blk++) {
        unsigned rec[4][8];
        for (int c = 0; c < 8; c++) {
            int coL = 16 * blk + c, coH = coL + 8;
            float aL[4], aH[4];
            #pragma unroll
            for (int p = 0; p < 4; p++) { aL[p] = sb[coL]; aH[p] = sb[coH]; }
            #pragma unroll
            for (int k = 0; k < 9; k++) {
                int ky = k / 3, kx = k - ky * 3;
                float wl = sw[coL * 9 + k], wh = sw[coH * 9 + k];
                #pragma unroll
                for (int p = 0; p < 4; p++) {
                    aL[p] = fmaf(inp[ky][p + kx], wl, aL[p]);
                    aH[p] = fmaf(inp[ky][p + kx], wh, aH[p]);
                }
            }
            int s = slot_of(c);
            #pragma unroll
            for (int p = 0; p < 4; p++)
                rec[p][s] = pack_h2(fmaxf(aL[p], 0.0f), fmaxf(aH[p], 0.0f));
        }
        #pragma unroll
        for (int p = 0; p < 4; p++) {
            size_t base = (((size_t)(b * 4 + blk)) * 65536 + (size_t)y * 256 + x4 + p) * 8;
            *(uint4*)(out + base)     = make_uint4(rec[p][0], rec[p][1], rec[p][2], rec[p][3]);
            *(uint4*)(out + base + 4) = make_uint4(rec[p][4], rec[p][5], rec[p][6], rec[p][7]);
        }
    }
}

// ---------------- unified weight pre-pack + acc zero ----------------
__global__ void pack_all_kernel(const float* __restrict__ w2,
                                const float* __restrict__ w3,
                                const float* __restrict__ w4,
                                unsigned* __restrict__ dst) {
    if (blockIdx.x == 0 && threadIdx.x == 0) {
        g_acc[0] = 0.0; g_acc[1] = 0.0; g_acc[2] = 0.0;
    }
    int total = 36864 + 147456 + 294912;
    for (int gidx = blockIdx.x * blockDim.x + threadIdx.x; gidx < total;
         gidx += gridDim.x * blockDim.x) {
        const float* w;
        int idx, Cin;
        if (gidx < 36864)        { w = w2; idx = gidx;          Cin = 64;  }
        else if (gidx < 184320)  { w = w3; idx = gidx - 36864;  Cin = 128; }
        else                     { w = w4; idx = gidx - 184320; Cin = 256; }
        int steps = Cin >> 4;
        int reg = idx & 3;
        int k4  = (idx >> 2) & 3;
        int q   = (idx >> 4) & 7;
        int f   = (idx >> 7) & 1;
        int mw  = (idx >> 8) & 1;
        int tap = (idx >> 9) % 9;
        int rest = idx / 4608;
        int step = rest % steps;
        int cb   = rest / steps;
        int co = cb * 64 + mw * 32 + f * 16 + q + (reg & 1) * 8;
        int c  = k4 + (reg >> 1) * 4;
        int ci_lo = step * 16 + c;
        float lo = w[((size_t)co * Cin + ci_lo) * 9 + tap];
        float hi = w[((size_t)co * Cin + ci_lo + 8) * 9 + tap];
        dst[gidx] = pack_h2(lo, hi);
    }
}

// ---------------- tensor-core 3x3 SAME conv (fp16 m16n8k16) ----------------
// 256 thr = 8 warps (2M x 4N), 128x2 strip tiles, 64 co/CTA, K=16/step.
// Multi-tile: each CTA processes nt consecutive y-pair tiles with the 3-stage
// cp.async ring continuing across tile boundaries (prologue amortized).
// MODE 0: store ; 1: diff-reduce vs ref ; 2: in-register 2x2 maxpool (W=256).
// MODE 2 remaps the warp N-footprint to 32 cols x 2 rows so each thread holds
// its full 2x2 pool block in registers (smem-free epilogue).
template<int W, int MODE>
__global__ __launch_bounds__(256, 2) void conv_mma(
    const unsigned* __restrict__ in, const unsigned* __restrict__ wpack,
    const float* __restrict__ bias,
    unsigned* __restrict__ out, const unsigned* __restrict__ ref,
    int Cin, int Cout, int nt)
{
    constexpr int H = W;
    constexpr int HW = W * W;
    constexpr int SCOLS = 130;
    constexpr int NPIX  = 4 * SCOLS;         // 520
    constexpr int SIN_U = NPIX * 8;          // 4160
    constexpr int SW_U  = 9 * 512;           // 4608
    constexpr int STRIPS = W >> 7;

    extern __shared__ unsigned smem_u[];
    unsigned* s_in = smem_u;                 // 3 buffers
    unsigned* s_w  = smem_u + 3 * SIN_U;     // 3 buffers
    __shared__ float s_red[32];

    int tid = threadIdx.x;
    int warp = tid >> 5;
    int lane = tid & 31;
    int q  = lane >> 2;
    int k4 = lane & 3;
    int mw = warp & 1;
    int nw = warp >> 1;
    int mwoff = mw * 32;
    int nwoff = nw * 64;

    int strip = blockIdx.x % STRIPS;
    int ybase = (blockIdx.x / STRIPS) * nt;   // first y-pair of this CTA
    int c0 = strip << 7;
    int cb  = blockIdx.y;
    int co0 = cb * 64;
    int b   = blockIdx.z;
    int steps = Cin >> 4;
    int total = steps * nt;

    unsigned s_in_u = (unsigned)__cvta_generic_to_shared(s_in);
    unsigned s_w_u  = (unsigned)__cvta_generic_to_shared(s_w);

    int awb0 = ((mw * 2 + 0) * 8 + q) * 16 + k4 * 4;
    int awb1 = awb0 + 128;

    int bb[8];
    #pragma unroll
    for (int nf = 0; nf < 8; nf++) {
        int ry, col;
        if (MODE == 2) { ry = nf >> 2; col = nw * 32 + (nf & 3) * 8; }
        else { int base = nwoff + nf * 8; ry = base >> 7; col = base & 127; }
        bb[nf] = ((ry * SCOLS + col) + q) * 8 + 2 * k4;
    }

    float acc[2][8][4];
    #pragma unroll
    for (int f = 0; f < 2; f++)
        #pragma unroll
        for (int nf = 0; nf < 8; nf++)
            #pragma unroll
            for (int e = 0; e < 4; e++) acc[f][nf][e] = 0.0f;

    const unsigned* inb = in + (size_t)b * (Cin >> 4) * HW * 8;
    const unsigned* wblk = wpack + (size_t)cb * steps * 4608;

    auto stage = [&](int g, int buf) {
        int tile = g / steps;
        int s    = g - tile * steps;
        int y0   = (ybase + tile) * 2;
        const unsigned* pbase = inb + (size_t)s * HW * 8;
        unsigned ibase = s_in_u + buf * SIN_U * 4;
        #pragma unroll 4
        for (int i = tid; i < NPIX * 2; i += 256) {
            int p = i >> 1;
            int half = i & 1;
            int r = p / SCOLS, cc = p - r * SCOLS;
            int gy = y0 - 1 + r;
            int gx = c0 + cc - 1;
            bool ok = ((unsigned)gy < (unsigned)H) && ((unsigned)gx < (unsigned)W);
            const unsigned* src = pbase + (size_t)(ok ? (gy * W + gx) : 0) * 8 + half * 4;
            cp_async16z(ibase + (unsigned)(p * 8 + half * 4) * 4, src, ok);
        }
        unsigned wbase = s_w_u + buf * SW_U * 4;
        const unsigned* wsrc = wblk + (size_t)s * 4608;
        #pragma unroll
        for (int i = tid; i < 1152; i += 256)
            cp_async16(wbase + (unsigned)i * 16, wsrc + i * 4);
    };

    stage(0, 0);
    cp_commit();
    if (total > 1) { stage(1, 1); cp_commit(); }

    int buf = 0;
    int sl = slot_of(q);
    for (int g = 0; g < total; g++) {
        if (g + 1 < total) { cp_wait<1>(); } else { cp_wait<0>(); }
        __syncthreads();
        if (g + 2 < total) {
            int nbuf = buf + 2; if (nbuf >= 3) nbuf -= 3;
            stage(g + 2, nbuf);
            cp_commit();
        }

        const unsigned* bin = s_in + buf * SIN_U;
        const unsigned* bw  = s_w  + buf * SW_U;

        #pragma unroll
        for (int tap = 0; tap < 9; tap++) {
            const int ky = tap / 3, kx = tap - ky * 3;
            const int toff = (ky * SCOLS + kx) * 8;
            uint4 af0 = *(const uint4*)(bw + tap * 512 + awb0);
            uint4 af1 = *(const uint4*)(bw + tap * 512 + awb1);
            #pragma unroll
            for (int nf = 0; nf < 8; nf++) {
                uint2 bv = *(const uint2*)(bin + bb[nf] + toff);
                mma_f16(acc[0][nf], af0, bv);
                mma_f16(acc[1][nf], af1, bv);
            }
        }
        buf++; if (buf >= 3) buf = 0;

        if (g - (g / steps) * steps == steps - 1) {
            // ---- per-tile epilogue ----
            int tile = g / steps;
            int ypair = ybase + tile;
            int y0 = ypair * 2;
            if (MODE == 0) {
                #pragma unroll
                for (int f = 0; f < 2; f++) {
                    int coL = co0 + mwoff + f * 16 + q;
                    float bv0 = __ldg(&bias[coL]);
                    float bv8 = __ldg(&bias[coL + 8]);
                    int plane = (co0 + mwoff + f * 16) >> 4;
                    unsigned* pl = out + ((size_t)b * (Cout >> 4) + plane) * HW * 8;
                    #pragma unroll
                    for (int nf = 0; nf < 8; nf++) {
                        int n = nwoff + nf * 8 + 2 * k4;
                        int idx = (y0 + (n >> 7)) * W + c0 + (n & 127);
                        pl[(size_t)idx * 8 + sl] =
                            pack_h2(fmaxf(acc[0][nf][0] * (f == 0) + acc[1][nf][0] * (f == 1) + bv0, 0.0f),
                                    fmaxf(acc[0][nf][2] * (f == 0) + acc[1][nf][2] * (f == 1) + bv8, 0.0f));
                        pl[(size_t)(idx + 1) * 8 + sl] =
                            pack_h2(fmaxf(acc[0][nf][1] * (f == 0) + acc[1][nf][1] * (f == 1) + bv0, 0.0f),
                                    fmaxf(acc[0][nf][3] * (f == 0) + acc[1][nf][3] * (f == 1) + bv8, 0.0f));
                    }
                }
            } else if (MODE == 1) {
                float lsum = 0.0f;
                #pragma unroll
                for (int f = 0; f < 2; f++) {
                    int coL = co0 + mwoff + f * 16 + q;
                    float bv0 = __ldg(&bias[coL]);
                    float bv8 = __ldg(&bias[coL + 8]);
                    int plane = (co0 + mwoff + f * 16) >> 4;
                    const unsigned* pl = ref + ((size_t)b * (Cout >> 4) + plane) * HW * 8;
                    #pragma unroll
                    for (int nf = 0; nf < 8; nf++) {
                        int n = nwoff + nf * 8 + 2 * k4;
                        int idx = (y0 + (n >> 7)) * W + c0 + (n & 127);
                        float2 r0 = unpack_h2(pl[(size_t)idx * 8 + sl]);
                        float2 r1 = unpack_h2(pl[(size_t)(idx + 1) * 8 + sl]);
                        float d0 = h16r(fmaxf(acc[f][nf][0] + bv0, 0.0f)) - r0.x;
                        float d1 = h16r(fmaxf(acc[f][nf][2] + bv8, 0.0f)) - r0.y;
                        float d2 = h16r(fmaxf(acc[f][nf][1] + bv0, 0.0f)) - r1.x;
                        float d3 = h16r(fmaxf(acc[f][nf][3] + bv8, 0.0f)) - r1.y;
                        lsum = fmaf(d0, d0, lsum);
                        lsum = fmaf(d1, d1, lsum);
                        lsum = fmaf(d2, d2, lsum);
                        lsum = fmaf(d3, d3, lsum);
                    }
                }
                float tot = block_reduce_sum256(lsum, s_red, tid);
                if (tid == 0) atomicAdd(&g_acc[2], (double)tot);
            } else {
                // MODE 2: in-register 2x2 maxpool, smem-free
                #pragma unroll
                for (int f = 0; f < 2; f++) {
                    int coL = co0 + mwoff + f * 16 + q;
                    float bv0 = __ldg(&bias[coL]);
                    float bv8 = __ldg(&bias[coL + 8]);
                    int lp = ((mwoff + f * 16) >> 4) * 8 + q;
                    int pl_loc = lp >> 3, cch = lp & 7;
                    unsigned* pl = out + (((size_t)b * 8 + cb * 4 + pl_loc)) * 16384 * 8;
                    int slp = slot_of(cch);
                    #pragma unroll
                    for (int nf = 0; nf < 4; nf++) {
                        float v0 = fmaxf(acc[f][nf][0], acc[f][nf + 4][0]);
                        float v1 = fmaxf(acc[f][nf][1], acc[f][nf + 4][1]);
                        float v2 = fmaxf(acc[f][nf][2], acc[f][nf + 4][2]);
                        float v3 = fmaxf(acc[f][nf][3], acc[f][nf + 4][3]);
                        float plo = fmaxf(fmaxf(v0, v1) + bv0, 0.0f);
                        float phi = fmaxf(fmaxf(v2, v3) + bv8, 0.0f);
                        int X = nw * 16 + nf * 4 + k4;
                        int pidx = ypair * 128 + (c0 >> 1) + X;
                        pl[(size_t)pidx * 8 + slp] = pack_h2(plo, phi);
                    }
                }
            }
            #pragma unroll
            for (int f = 0; f < 2; f++)
                #pragma unroll
                for (int nf = 0; nf < 8; nf++)
                    #pragma unroll
                    for (int e = 0; e < 4; e++) acc[f][nf][e] = 0.0f;
        }
    }
}

// ---------------- finalize ----------------
__global__ void finalize_kernel(float* out, int out_size) {
    double mse    = g_acc[0] / 524288.0;
    double ssim_l = 1.0 - g_acc[1] / 500000.0;
    double perc   = g_acc[2] / 33554432.0;
    double total  = mse + 0.5 * ssim_l + 0.1 * perc;
    float vals[4] = {(float)total, (float)mse, (float)ssim_l, (float)perc};
    for (int i = 0; i < 4 && i < out_size; i++) out[i] = vals[i];
}

// ---------------- launcher ----------------
extern "C" void kernel_launch(void* const* d_in, const int* in_sizes, int n_in,
                              void* d_out, int out_size) {
    (void)in_sizes; (void)n_in;
    const float* sr = (const float*)d_in[0];
    const float* hr = (const float*)d_in[1];
    const float* w1 = (const float*)d_in[2];
    const float* b1 = (const float*)d_in[3];
    const float* w2 = (const float*)d_in[4];
    const float* b2 = (const float*)d_in[5];
    const float* w3 = (const float*)d_in[6];
    const float* b3 = (const float*)d_in[7];
    const float* w4 = (const float*)d_in[8];
    const float* b4 = (const float*)d_in[9];
    float* out = (float*)d_out;

    unsigned *A, *P, *C, *D, *WP;
    cudaGetSymbolAddress((void**)&A, g_bufA);
    cudaGetSymbolAddress((void**)&P, g_bufP);
    cudaGetSymbolAddress((void**)&C, g_bufC);
    cudaGetSymbolAddress((void**)&D, g_bufD);
    cudaGetSymbolAddress((void**)&WP, g_wpk);
    unsigned* WP2 = WP;             // 36864 u32
    unsigned* WP3 = WP + 36864;     // 147456 u32
    unsigned* WP4 = WP + 184320;    // 294912 u32

    const int smem = (3 * 4160 + 3 * 4608) * 4;   // 105216 B
    cudaFuncSetAttribute(conv_mma<256, 2>, cudaFuncAttributeMaxDynamicSharedMemorySize, smem);
    cudaFuncSetAttribute(conv_mma<128, 0>, cudaFuncAttributeMaxDynamicSharedMemorySize, smem);
    cudaFuncSetAttribute(conv_mma<128, 1>, cudaFuncAttributeMaxDynamicSharedMemorySize, smem);

    pack_all_kernel<<<1872, 256>>>(w2, w3, w4, WP);
    conv1_kernel<<<1024, 256>>>(sr, hr, w1, b1, A);
    // conv2 + in-register pool, both images, 4 tiles/CTA (16 steps)
    conv_mma<256, 2><<<dim3(64, 2, 16), 256, smem>>>(A, WP2, b2, P, nullptr, 64, 128, 4);
    // conv3 both images, 2 tiles/CTA (16 steps)
    conv_mma<128, 0><<<dim3(32, 4, 16), 256, smem>>>(P, WP3, b3, C, nullptr, 128, 256, 2);
    // conv4 sr: store D
    conv_mma<128, 0><<<dim3(64, 4, 8), 256, smem>>>(C, WP4, b4, D, nullptr, 256, 256, 1);
    ssim_kernel<<<dim3(16, 16, 8), dim3(16, 16)>>>(sr, hr);
    // conv4 hr: diff vs D
    conv_mma<128, 1><<<dim3(64, 4, 8), 256, smem>>>(C + (size_t)8 * 16 * 16384 * 8,
                                                    WP4, b4, nullptr, D, 256, 256, 1);

    finalize_kernel<<<1, 1>>>(out, out_size);
}